// round 1
// baseline (speedup 1.0000x reference)
#include <cuda_runtime.h>
#include <math.h>

// Problem constants
#define BB 2
#define SS 2048
#define DM 512
#define HH 8
#define DH 64
#define CH 64               // chunk length for linear-attention scan
#define NC (SS/CH)          // 32 chunks
#define BH (BB*HH)          // 16 (b,h) pairs

// Scratch (device globals — no allocation allowed)
__device__ float g_q  [BH*SS*DH];      // [b,h,s,d]  elu+1 applied
__device__ float g_k  [BH*SS*DH];
__device__ float g_v  [BH*SS*DH];
__device__ float g_ckv[BH*NC*DH*DH];   // per-chunk  K^T V
__device__ float g_cks[BH*NC*DH];      // per-chunk  sum_s k
__device__ float g_pkv[BH*NC*DH*DH];   // exclusive prefix of g_ckv
__device__ float g_pks[BH*NC*DH];
__device__ float g_ctx[BB*SS*DM];      // context, [b,s,h*64+d] == d_model layout

// ---------------------------------------------------------------------------
// Kernel 1: fused QKV projection.  out[n, j] = x[n,:] . W[j,:] + b[j]
// j in [0,512) -> q (elu+1), [512,1024) -> k (elu+1), [1024,1536) -> v
// NT GEMM, 64x64 tile, BK=16, 256 threads, 4x4 per thread.
// ---------------------------------------------------------------------------
__global__ __launch_bounds__(256) void proj_kernel(
    const float* __restrict__ x,  const float* __restrict__ Wqk,
    const float* __restrict__ bqk, const float* __restrict__ Wv,
    const float* __restrict__ bv)
{
    __shared__ float sA[16][68];
    __shared__ float sB[16][68];
    const int jt  = blockIdx.x * 64;          // over 1536
    const int nt  = blockIdx.y * 64;          // over 4096
    const int tid = threadIdx.x;
    const int tx  = tid & 15, ty = tid >> 4;
    const int lr  = tid >> 2;                 // 0..63
    const int lk  = (tid & 3) << 2;           // 0,4,8,12

    const float* arow = x + (size_t)(nt + lr) * DM + lk;
    const int jg = jt + lr;
    const float* brow = (jg < 2*DM ? Wqk + (size_t)jg * DM
                                   : Wv  + (size_t)(jg - 2*DM) * DM) + lk;
    float acc[4][4] = {};
    for (int k0 = 0; k0 < DM; k0 += 16) {
        float4 a4 = *(const float4*)(arow + k0);
        float4 b4 = *(const float4*)(brow + k0);
        __syncthreads();
        sA[lk+0][lr]=a4.x; sA[lk+1][lr]=a4.y; sA[lk+2][lr]=a4.z; sA[lk+3][lr]=a4.w;
        sB[lk+0][lr]=b4.x; sB[lk+1][lr]=b4.y; sB[lk+2][lr]=b4.z; sB[lk+3][lr]=b4.w;
        __syncthreads();
#pragma unroll
        for (int kk = 0; kk < 16; kk++) {
            float4 av  = *(const float4*)&sA[kk][ty<<2];
            float4 bv4 = *(const float4*)&sB[kk][tx<<2];
            float a[4] = {av.x, av.y, av.z, av.w};
            float b[4] = {bv4.x, bv4.y, bv4.z, bv4.w};
#pragma unroll
            for (int i=0;i<4;i++)
#pragma unroll
                for (int j=0;j<4;j++) acc[i][j] = fmaf(a[i], b[j], acc[i][j]);
        }
    }
#pragma unroll
    for (int i=0;i<4;i++) {
        int n  = nt + (ty<<2) + i;
        int b_ = n >> 11;                 // /S (2048)
        int s_ = n & (SS-1);
#pragma unroll
        for (int j=0;j<4;j++) {
            int jgo = jt + (tx<<2) + j;
            if (jgo < DM) {
                float val = acc[i][j] + bqk[jgo];
                val = (val > 0.f) ? (val + 1.f) : expf(val);     // elu+1
                int h = jgo >> 6, d = jgo & 63;
                g_q[((size_t)(b_*HH + h)*SS + s_)*DH + d] = val;
            } else if (jgo < 2*DM) {
                float val = acc[i][j] + bqk[jgo];
                val = (val > 0.f) ? (val + 1.f) : expf(val);
                int jq = jgo - DM;
                int h = jq >> 6, d = jq & 63;
                g_k[((size_t)(b_*HH + h)*SS + s_)*DH + d] = val;
            } else {
                int jv = jgo - 2*DM;
                float val = acc[i][j] + bv[jv];
                int h = jv >> 6, d = jv & 63;
                g_v[((size_t)(b_*HH + h)*SS + s_)*DH + d] = val;
            }
        }
    }
}

// ---------------------------------------------------------------------------
// Kernel 2: per-chunk state  KV[d1][d2] = sum_s k[s][d1] v[s][d2], ksum[d].
// One CTA per (chunk, bh). 256 threads, 4x4 per thread over 64x64 output.
// ---------------------------------------------------------------------------
__global__ __launch_bounds__(256) void chunkkv_kernel()
{
    __shared__ float sK[CH][68];
    __shared__ float sV[CH][68];
    const int c  = blockIdx.x, bh = blockIdx.y;
    const int tid = threadIdx.x;
    const int tx = tid & 15, ty = tid >> 4;
    const float* kp = g_k + ((size_t)bh*SS + (size_t)c*CH)*DH;
    const float* vp = g_v + ((size_t)bh*SS + (size_t)c*CH)*DH;
    for (int idx = tid; idx < CH*16; idx += 256) {
        int r = idx >> 4, c4 = (idx & 15) << 2;
        *(float4*)&sK[r][c4] = *(const float4*)(kp + r*DH + c4);
        *(float4*)&sV[r][c4] = *(const float4*)(vp + r*DH + c4);
    }
    __syncthreads();
    float acc[4][4] = {};
#pragma unroll 4
    for (int s = 0; s < CH; s++) {
        float a[4];
#pragma unroll
        for (int i=0;i<4;i++) a[i] = sK[s][(ty<<2)+i];
        float4 b4 = *(const float4*)&sV[s][tx<<2];
        float b[4] = {b4.x,b4.y,b4.z,b4.w};
#pragma unroll
        for (int i=0;i<4;i++)
#pragma unroll
            for (int j=0;j<4;j++) acc[i][j] = fmaf(a[i], b[j], acc[i][j]);
    }
    float* dst = g_ckv + ((size_t)bh*NC + c)*DH*DH;
#pragma unroll
    for (int i=0;i<4;i++) {
        float4 o = {acc[i][0],acc[i][1],acc[i][2],acc[i][3]};
        *(float4*)(dst + (size_t)((ty<<2)+i)*DH + (tx<<2)) = o;
    }
    if (tid < DH) {
        float s = 0.f;
        for (int r = 0; r < CH; r++) s += sK[r][tid];
        g_cks[((size_t)bh*NC + c)*DH + tid] = s;
    }
}

// ---------------------------------------------------------------------------
// Kernel 3: exclusive prefix scan over chunks (per bh). 16 CTAs.
// ---------------------------------------------------------------------------
__global__ __launch_bounds__(256) void scan_kernel()
{
    const int bh = blockIdx.x;
    const int tid = threadIdx.x;
    const size_t base = (size_t)bh * NC;
    for (int e = tid; e < DH*DH; e += 256) {
        float run = 0.f;
        for (int c = 0; c < NC; c++) {
            size_t o = (base + c)*DH*DH + e;
            g_pkv[o] = run;
            run += g_ckv[o];
        }
    }
    if (tid < DH) {
        float run = 0.f;
        for (int c = 0; c < NC; c++) {
            size_t o = (base + c)*DH + tid;
            g_pks[o] = run;
            run += g_cks[o];
        }
    }
}

// ---------------------------------------------------------------------------
// Kernel 4: per-chunk context.
//  S[t][s] = q_t . k_s  (tril masked, local)
//  den[t]  = rowsum(S) + q_t . ksum_pre
//  ctx[t]  = (S @ v + q @ KV_pre) / den[t]
// Dynamic smem: sQ[t][e], sB (k^T then v), sS[t][s], sC (KV_pre), + ksum, den
// ---------------------------------------------------------------------------
#define CTX_SMEM_BYTES ((4*64*68 + 128) * 4)

__global__ __launch_bounds__(256) void ctx_kernel()
{
    extern __shared__ float sm[];
    float* sQ   = sm;                 // [64][68] natural [t][e]
    float* sB   = sm + 64*68;         // phase1: k transposed [e][s]; phase2: v [s][d]
    float* sS   = sm + 2*64*68;       // [t][s]
    float* sC   = sm + 3*64*68;       // KV_pre [e][d]
    float* sKs  = sm + 4*64*68;       // [64]
    float* sDen = sKs + 64;           // [64]

    const int c  = blockIdx.x, bh = blockIdx.y;
    const int tid = threadIdx.x, tx = tid & 15, ty = tid >> 4;

    const float* qp  = g_q   + ((size_t)bh*SS + (size_t)c*CH)*DH;
    const float* kp  = g_k   + ((size_t)bh*SS + (size_t)c*CH)*DH;
    const float* vp  = g_v   + ((size_t)bh*SS + (size_t)c*CH)*DH;
    const float* kvp = g_pkv + ((size_t)bh*NC + c)*DH*DH;
    const float* ksp = g_pks + ((size_t)bh*NC + c)*DH;

    // load q natural, k transposed
    for (int idx = tid; idx < 1024; idx += 256) {
        int r = idx >> 4, c4 = (idx & 15) << 2;
        float4 q4 = *(const float4*)(qp + r*DH + c4);
        *(float4*)&sQ[r*68 + c4] = q4;
        float4 k4 = *(const float4*)(kp + r*DH + c4);
        sB[(c4+0)*68 + r] = k4.x;
        sB[(c4+1)*68 + r] = k4.y;
        sB[(c4+2)*68 + r] = k4.z;
        sB[(c4+3)*68 + r] = k4.w;
    }
    if (tid < DH) sKs[tid] = ksp[tid];
    __syncthreads();

    // phase 2: S = q k^T, tril mask
    {
        float acc[4][4] = {};
#pragma unroll 4
        for (int e = 0; e < DH; e++) {
            float a[4];
#pragma unroll
            for (int i=0;i<4;i++) a[i] = sQ[((ty<<2)+i)*68 + e];
            float4 b4 = *(const float4*)&sB[e*68 + (tx<<2)];
            float b[4] = {b4.x,b4.y,b4.z,b4.w};
#pragma unroll
            for (int i=0;i<4;i++)
#pragma unroll
                for (int j=0;j<4;j++) acc[i][j] = fmaf(a[i], b[j], acc[i][j]);
        }
        const int tb = ty<<2, sb = tx<<2;
#pragma unroll
        for (int i=0;i<4;i++)
#pragma unroll
            for (int j=0;j<4;j++)
                sS[(tb+i)*68 + sb+j] = (sb+j <= tb+i) ? acc[i][j] : 0.f;
    }
    __syncthreads();

    // phase 3: den (64 threads) ; phase 4: reload sB <- v, sC <- KV_pre (all)
    if (tid < DH) {
        float d = 0.f;
        for (int s = 0; s < CH; s++) d += sS[tid*68 + s];
        for (int e = 0; e < DH; e++) d += sQ[tid*68 + e] * sKs[e];
        sDen[tid] = d;
    }
    for (int idx = tid; idx < 1024; idx += 256) {
        int r = idx >> 4, c4 = (idx & 15) << 2;
        *(float4*)&sB[r*68 + c4] = *(const float4*)(vp  + r*DH + c4);
        *(float4*)&sC[r*68 + c4] = *(const float4*)(kvp + r*DH + c4);
    }
    __syncthreads();

    // phase 5: ctx = (S @ v + q @ KV_pre) / den
    float acc[4][4] = {};
#pragma unroll 4
    for (int s = 0; s < CH; s++) {
        float a[4];
#pragma unroll
        for (int i=0;i<4;i++) a[i] = sS[((ty<<2)+i)*68 + s];
        float4 b4 = *(const float4*)&sB[s*68 + (tx<<2)];
        float b[4] = {b4.x,b4.y,b4.z,b4.w};
#pragma unroll
        for (int i=0;i<4;i++)
#pragma unroll
            for (int j=0;j<4;j++) acc[i][j] = fmaf(a[i], b[j], acc[i][j]);
    }
#pragma unroll 4
    for (int e = 0; e < DH; e++) {
        float a[4];
#pragma unroll
        for (int i=0;i<4;i++) a[i] = sQ[((ty<<2)+i)*68 + e];
        float4 b4 = *(const float4*)&sC[e*68 + (tx<<2)];
        float b[4] = {b4.x,b4.y,b4.z,b4.w};
#pragma unroll
        for (int i=0;i<4;i++)
#pragma unroll
            for (int j=0;j<4;j++) acc[i][j] = fmaf(a[i], b[j], acc[i][j]);
    }
    const int b_ = bh >> 3, h = bh & 7;
#pragma unroll
    for (int i=0;i<4;i++) {
        int t = (ty<<2) + i;
        float inv = 1.f / sDen[t];
        int sg = c*CH + t;
        float4 o = {acc[i][0]*inv, acc[i][1]*inv, acc[i][2]*inv, acc[i][3]*inv};
        *(float4*)(g_ctx + ((size_t)(b_*SS + sg))*DM + h*DH + (tx<<2)) = o;
    }
}

// ---------------------------------------------------------------------------
// Kernel 5: output projection.  out = ctx @ Wo^T + bo
// ---------------------------------------------------------------------------
__global__ __launch_bounds__(256) void out_kernel(
    const float* __restrict__ Wo, const float* __restrict__ bo,
    float* __restrict__ out)
{
    __shared__ float sA[16][68];
    __shared__ float sB[16][68];
    const int jt  = blockIdx.x * 64;          // over 512
    const int nt  = blockIdx.y * 64;          // over 4096
    const int tid = threadIdx.x;
    const int tx  = tid & 15, ty = tid >> 4;
    const int lr  = tid >> 2;
    const int lk  = (tid & 3) << 2;

    const float* arow = g_ctx + (size_t)(nt + lr) * DM + lk;
    const float* brow = Wo + (size_t)(jt + lr) * DM + lk;
    float acc[4][4] = {};
    for (int k0 = 0; k0 < DM; k0 += 16) {
        float4 a4 = *(const float4*)(arow + k0);
        float4 b4 = *(const float4*)(brow + k0);
        __syncthreads();
        sA[lk+0][lr]=a4.x; sA[lk+1][lr]=a4.y; sA[lk+2][lr]=a4.z; sA[lk+3][lr]=a4.w;
        sB[lk+0][lr]=b4.x; sB[lk+1][lr]=b4.y; sB[lk+2][lr]=b4.z; sB[lk+3][lr]=b4.w;
        __syncthreads();
#pragma unroll
        for (int kk = 0; kk < 16; kk++) {
            float4 av  = *(const float4*)&sA[kk][ty<<2];
            float4 bv4 = *(const float4*)&sB[kk][tx<<2];
            float a[4] = {av.x, av.y, av.z, av.w};
            float b[4] = {bv4.x, bv4.y, bv4.z, bv4.w};
#pragma unroll
            for (int i=0;i<4;i++)
#pragma unroll
                for (int j=0;j<4;j++) acc[i][j] = fmaf(a[i], b[j], acc[i][j]);
        }
    }
    const int jb = jt + (tx<<2);
    float4 bias = *(const float4*)(bo + jb);
#pragma unroll
    for (int i=0;i<4;i++) {
        int n = nt + (ty<<2) + i;
        float4 o = {acc[i][0]+bias.x, acc[i][1]+bias.y,
                    acc[i][2]+bias.z, acc[i][3]+bias.w};
        *(float4*)(out + (size_t)n*DM + jb) = o;
    }
}

// ---------------------------------------------------------------------------
extern "C" void kernel_launch(void* const* d_in, const int* in_sizes, int n_in,
                              void* d_out, int out_size)
{
    const float* x   = (const float*)d_in[0];
    const float* Wqk = (const float*)d_in[1];
    const float* bqk = (const float*)d_in[2];
    const float* Wv  = (const float*)d_in[3];
    const float* bv  = (const float*)d_in[4];
    const float* Wo  = (const float*)d_in[5];
    const float* bo  = (const float*)d_in[6];
    float* out = (float*)d_out;

    cudaFuncSetAttribute(ctx_kernel,
        cudaFuncAttributeMaxDynamicSharedMemorySize, CTX_SMEM_BYTES);

    proj_kernel<<<dim3(24, 64), 256>>>(x, Wqk, bqk, Wv, bv);
    chunkkv_kernel<<<dim3(NC, BH), 256>>>();
    scan_kernel<<<BH, 256>>>();
    ctx_kernel<<<dim3(NC, BH), 256, CTX_SMEM_BYTES>>>();
    out_kernel<<<dim3(8, 64), 256>>>(Wo, bo, out);
}

// round 5
// speedup vs baseline: 1.5770x; 1.5770x over previous
#include <cuda_runtime.h>
#include <math.h>
#include <stdint.h>

// Problem constants
#define BB 2
#define SS 2048
#define DM 512
#define HH 8
#define DH 64
#define CH 64               // chunk length for linear-attention scan
#define NC (SS/CH)          // 32 chunks
#define BH (BB*HH)          // 16 (b,h) pairs

// Scratch (device globals — no allocation allowed)
__device__ float g_q  [BH*SS*DH];      // [b,h,s,d]  elu+1 applied
__device__ float g_k  [BH*SS*DH];
__device__ float g_v  [BH*SS*DH];
__device__ float g_ckv[BH*NC*DH*DH];   // per-chunk  K^T V
__device__ float g_cks[BH*NC*DH];      // per-chunk  sum_s k
__device__ float g_pkv[BH*NC*DH*DH];   // exclusive prefix of g_ckv
__device__ float g_pks[BH*NC*DH];
__device__ float g_ctx[BB*SS*DM];      // context, [b,s,h*64+d] == d_model layout

// ===========================================================================
// tf32 mma.sync GEMM (sm_80-compatible PTX; no tcgen05 — target lacks 'a')
// C[128x128] = A[128xK] * B[128xK]^T  (NT), K = 512, BK = 32.
// 256 threads = 8 warps (2 M x 4 N), warp tile 64x32 (4x4 frags m16n8k8).
// A in smem row-major [m][BK], B as [n][BK]; row stride 36 floats (144 B)
// -> conflict-free ldmatrix (144 mod 128 = 16).
// ===========================================================================
#define BK 32
#define LDAPAD 36
#define TILE_BYTES (128*LDAPAD*4)          // 18432
#define GEMM_SMEM_BYTES (4*TILE_BYTES)     // 73728 (A0,B0,A1,B1)

__device__ __forceinline__ uint32_t smem_u32(const void* p) {
    uint32_t a;
    asm("{ .reg .u64 t; cvta.to.shared.u64 t, %1; cvt.u32.u64 %0, t; }"
        : "=r"(a) : "l"(p));
    return a;
}
__device__ __forceinline__ uint32_t f2tf32(float f) {
    uint32_t u;
    asm("cvt.rna.tf32.f32 %0, %1;" : "=r"(u) : "f"(f));
    return u;
}
__device__ __forceinline__ void ldsm_x4(uint32_t& r0, uint32_t& r1,
                                        uint32_t& r2, uint32_t& r3, uint32_t a) {
    asm volatile("ldmatrix.sync.aligned.m8n8.x4.shared.b16 {%0,%1,%2,%3}, [%4];"
                 : "=r"(r0), "=r"(r1), "=r"(r2), "=r"(r3) : "r"(a));
}
__device__ __forceinline__ void ldsm_x2(uint32_t& r0, uint32_t& r1, uint32_t a) {
    asm volatile("ldmatrix.sync.aligned.m8n8.x2.shared.b16 {%0,%1}, [%2];"
                 : "=r"(r0), "=r"(r1) : "r"(a));
}
__device__ __forceinline__ void mma_tf32(float& c0, float& c1, float& c2, float& c3,
                                         uint32_t a0, uint32_t a1, uint32_t a2, uint32_t a3,
                                         uint32_t b0, uint32_t b1) {
    asm volatile("mma.sync.aligned.m16n8k8.row.col.f32.tf32.tf32.f32 "
                 "{%0,%1,%2,%3}, {%4,%5,%6,%7}, {%8,%9}, {%0,%1,%2,%3};"
                 : "+f"(c0), "+f"(c1), "+f"(c2), "+f"(c3)
                 : "r"(a0), "r"(a1), "r"(a2), "r"(a3), "r"(b0), "r"(b1));
}

// MODE 0: proj (A=x, B=Wqk|Wv, epilogue bias+elu, scatter q/k/v)
// MODE 1: out  (A=g_ctx, B=Wo, epilogue bias, store out)
template<int MODE>
__global__ __launch_bounds__(256) void gemm_tf32(
    const float* __restrict__ A,  const float* __restrict__ B0,
    const float* __restrict__ B1, const float* __restrict__ bias0,
    const float* __restrict__ bias1, float* __restrict__ outp)
{
    extern __shared__ __align__(16) char smem[];
    const int tid = threadIdx.x;
    const int wid = tid >> 5, lane = tid & 31;
    const int wm = wid & 1, wn = wid >> 1;          // 2 x 4 warp grid
    const int jt = blockIdx.x * 128;
    const int nt = blockIdx.y * 128;

    const float* Ap = (MODE == 1) ? (const float*)g_ctx : A;

    // smem tiles: A0 | B0 | A1 | B1
    uint32_t sb = smem_u32(smem);
    const uint32_t sA[2] = { sb,                  sb + 2*TILE_BYTES };
    const uint32_t sB[2] = { sb + TILE_BYTES,     sb + 3*TILE_BYTES };
    float* cA[2] = { (float*)smem,                (float*)(smem + 2*TILE_BYTES) };
    float* cB[2] = { (float*)(smem + TILE_BYTES), (float*)(smem + 3*TILE_BYTES) };

    // per-thread gmem load rows: 4 float4 for A, 4 for B per BK-tile
    const float* rowA[4]; const float* rowB[4]; int wrow[4], wc4[4];
#pragma unroll
    for (int u = 0; u < 4; u++) {
        int idx = tid + u * 256;            // 0..1023
        int r = idx >> 3, c4 = idx & 7;     // row 0..127, float4 col 0..7
        wrow[u] = r; wc4[u] = c4;
        rowA[u] = Ap + (size_t)(nt + r) * DM + c4 * 4;
        if (MODE == 0) {
            int j = jt + r;
            rowB[u] = (j < 2 * DM ? B0 + (size_t)j * DM
                                  : B1 + (size_t)(j - 2 * DM) * DM) + c4 * 4;
        } else {
            rowB[u] = B0 + (size_t)(jt + r) * DM + c4 * 4;
        }
    }

    // ldmatrix lane address offsets (bytes within tile)
    const int g = lane >> 3, r8 = lane & 7;
    const uint32_t aoff = (uint32_t)((((g & 1) * 8 + r8) * LDAPAD + (g >> 1) * 4) * 4);
    const uint32_t boff = (uint32_t)(((lane & 7) * LDAPAD + ((lane >> 3) & 1) * 4) * 4);
    const uint32_t awarp = (uint32_t)(wm * 64 * LDAPAD * 4);
    const uint32_t bwarp = (uint32_t)(wn * 32 * LDAPAD * 4);

    float acc[4][4][4] = {};   // [mf][nf][c0..c3]

    // prologue: tile 0 -> buf 0
    {
        float4 av[4], bv[4];
#pragma unroll
        for (int u = 0; u < 4; u++) { av[u] = *(const float4*)rowA[u];
                                      bv[u] = *(const float4*)rowB[u]; }
#pragma unroll
        for (int u = 0; u < 4; u++) {
            float* pa = cA[0] + wrow[u] * LDAPAD + wc4[u] * 4;
            float* pb = cB[0] + wrow[u] * LDAPAD + wc4[u] * 4;
            ((uint32_t*)pa)[0] = f2tf32(av[u].x); ((uint32_t*)pa)[1] = f2tf32(av[u].y);
            ((uint32_t*)pa)[2] = f2tf32(av[u].z); ((uint32_t*)pa)[3] = f2tf32(av[u].w);
            ((uint32_t*)pb)[0] = f2tf32(bv[u].x); ((uint32_t*)pb)[1] = f2tf32(bv[u].y);
            ((uint32_t*)pb)[2] = f2tf32(bv[u].z); ((uint32_t*)pb)[3] = f2tf32(bv[u].w);
        }
        __syncthreads();
    }

    for (int it = 0; it < 16; it++) {
        const int buf = it & 1;
        float4 av[4], bv[4];
        if (it < 15) {
            const int k0 = (it + 1) * BK;
#pragma unroll
            for (int u = 0; u < 4; u++) { av[u] = *(const float4*)(rowA[u] + k0);
                                          bv[u] = *(const float4*)(rowB[u] + k0); }
        }
        // compute on buf
        const uint32_t abase = sA[buf] + awarp + aoff;
        const uint32_t bbase = sB[buf] + bwarp + boff;
#pragma unroll
        for (int kk = 0; kk < 4; kk++) {
            uint32_t afr[4][4], bfr[4][2];
#pragma unroll
            for (int mf = 0; mf < 4; mf++)
                ldsm_x4(afr[mf][0], afr[mf][1], afr[mf][2], afr[mf][3],
                        abase + (uint32_t)(mf * 16 * LDAPAD * 4) + kk * 32);
#pragma unroll
            for (int nf = 0; nf < 4; nf++)
                ldsm_x2(bfr[nf][0], bfr[nf][1],
                        bbase + (uint32_t)(nf * 8 * LDAPAD * 4) + kk * 32);
#pragma unroll
            for (int mf = 0; mf < 4; mf++)
#pragma unroll
                for (int nf = 0; nf < 4; nf++)
                    mma_tf32(acc[mf][nf][0], acc[mf][nf][1],
                             acc[mf][nf][2], acc[mf][nf][3],
                             afr[mf][0], afr[mf][1], afr[mf][2], afr[mf][3],
                             bfr[nf][0], bfr[nf][1]);
        }
        if (it < 15) {
            const int nb = buf ^ 1;
#pragma unroll
            for (int u = 0; u < 4; u++) {
                float* pa = cA[nb] + wrow[u] * LDAPAD + wc4[u] * 4;
                float* pb = cB[nb] + wrow[u] * LDAPAD + wc4[u] * 4;
                ((uint32_t*)pa)[0] = f2tf32(av[u].x); ((uint32_t*)pa)[1] = f2tf32(av[u].y);
                ((uint32_t*)pa)[2] = f2tf32(av[u].z); ((uint32_t*)pa)[3] = f2tf32(av[u].w);
                ((uint32_t*)pb)[0] = f2tf32(bv[u].x); ((uint32_t*)pb)[1] = f2tf32(bv[u].y);
                ((uint32_t*)pb)[2] = f2tf32(bv[u].z); ((uint32_t*)pb)[3] = f2tf32(bv[u].w);
            }
        }
        __syncthreads();
    }

    // Epilogue. c0,c1 -> (row l/4,     cols 2(l%4)+{0,1})
    //           c2,c3 -> (row l/4 + 8, cols 2(l%4)+{0,1})
    const int rl = lane >> 2, cl = (lane & 3) * 2;
#pragma unroll
    for (int mf = 0; mf < 4; mf++) {
#pragma unroll
        for (int nf = 0; nf < 4; nf++) {
            const int j0 = jt + wn * 32 + nf * 8 + cl;
#pragma unroll
            for (int half = 0; half < 2; half++) {
                const int row = nt + wm * 64 + mf * 16 + rl + half * 8;
                float v0 = acc[mf][nf][half * 2 + 0];
                float v1 = acc[mf][nf][half * 2 + 1];
                if (MODE == 0) {
                    const int b_ = row >> 11, s_ = row & (SS - 1);
                    if (j0 < 2 * DM) {
                        v0 += bias0[j0]; v1 += bias0[j0 + 1];
                        v0 = (v0 > 0.f) ? v0 + 1.f : expf(v0);
                        v1 = (v1 > 0.f) ? v1 + 1.f : expf(v1);
                        int jm = j0 & (DM - 1);
                        int h = jm >> 6, d = jm & 63;
                        float* dst = (j0 < DM ? g_q : g_k)
                                   + (((size_t)(b_ * HH + h) * SS + s_) * DH + d);
                        *(float2*)dst = make_float2(v0, v1);
                    } else {
                        int jm = j0 - 2 * DM;
                        v0 += bias1[jm]; v1 += bias1[jm + 1];
                        int h = jm >> 6, d = jm & 63;
                        float* dst = g_v + (((size_t)(b_ * HH + h) * SS + s_) * DH + d);
                        *(float2*)dst = make_float2(v0, v1);
                    }
                } else {
                    float2 bi = *(const float2*)(bias0 + j0);
                    *(float2*)(outp + (size_t)row * DM + j0) =
                        make_float2(v0 + bi.x, v1 + bi.y);
                }
            }
        }
    }
}

// ---------------------------------------------------------------------------
// Kernel 2: per-chunk state  KV[d1][d2] = sum_s k[s][d1] v[s][d2], ksum[d].
// ---------------------------------------------------------------------------
__global__ __launch_bounds__(256) void chunkkv_kernel()
{
    __shared__ float sK[CH][68];
    __shared__ float sV[CH][68];
    const int c  = blockIdx.x, bh = blockIdx.y;
    const int tid = threadIdx.x;
    const int tx = tid & 15, ty = tid >> 4;
    const float* kp = g_k + ((size_t)bh*SS + (size_t)c*CH)*DH;
    const float* vp = g_v + ((size_t)bh*SS + (size_t)c*CH)*DH;
    for (int idx = tid; idx < CH*16; idx += 256) {
        int r = idx >> 4, c4 = (idx & 15) << 2;
        *(float4*)&sK[r][c4] = *(const float4*)(kp + r*DH + c4);
        *(float4*)&sV[r][c4] = *(const float4*)(vp + r*DH + c4);
    }
    __syncthreads();
    float acc[4][4] = {};
#pragma unroll 4
    for (int s = 0; s < CH; s++) {
        float a[4];
#pragma unroll
        for (int i=0;i<4;i++) a[i] = sK[s][(ty<<2)+i];
        float4 b4 = *(const float4*)&sV[s][tx<<2];
        float b[4] = {b4.x,b4.y,b4.z,b4.w};
#pragma unroll
        for (int i=0;i<4;i++)
#pragma unroll
            for (int j=0;j<4;j++) acc[i][j] = fmaf(a[i], b[j], acc[i][j]);
    }
    float* dst = g_ckv + ((size_t)bh*NC + c)*DH*DH;
#pragma unroll
    for (int i=0;i<4;i++) {
        float4 o = {acc[i][0],acc[i][1],acc[i][2],acc[i][3]};
        *(float4*)(dst + (size_t)((ty<<2)+i)*DH + (tx<<2)) = o;
    }
    if (tid < DH) {
        float s = 0.f;
        for (int r = 0; r < CH; r++) s += sK[r][tid];
        g_cks[((size_t)bh*NC + c)*DH + tid] = s;
    }
}

// ---------------------------------------------------------------------------
// Kernel 3: exclusive prefix scan over chunks (per bh). 16 CTAs.
// ---------------------------------------------------------------------------
__global__ __launch_bounds__(256) void scan_kernel()
{
    const int bh = blockIdx.x;
    const int tid = threadIdx.x;
    const size_t base = (size_t)bh * NC;
    for (int e = tid; e < DH*DH; e += 256) {
        float run = 0.f;
        for (int c = 0; c < NC; c++) {
            size_t o = (base + c)*DH*DH + e;
            g_pkv[o] = run;
            run += g_ckv[o];
        }
    }
    if (tid < DH) {
        float run = 0.f;
        for (int c = 0; c < NC; c++) {
            size_t o = (base + c)*DH + tid;
            g_pks[o] = run;
            run += g_cks[o];
        }
    }
}

// ---------------------------------------------------------------------------
// Kernel 4: per-chunk context.
// ---------------------------------------------------------------------------
#define CTX_SMEM_BYTES ((4*64*68 + 128) * 4)

__global__ __launch_bounds__(256) void ctx_kernel()
{
    extern __shared__ float sm[];
    float* sQ   = sm;                 // [64][68] natural [t][e]
    float* sB   = sm + 64*68;         // phase1: k transposed [e][s]; phase2: v [s][d]
    float* sS   = sm + 2*64*68;       // [t][s]
    float* sC   = sm + 3*64*68;       // KV_pre [e][d]
    float* sKs  = sm + 4*64*68;       // [64]
    float* sDen = sKs + 64;           // [64]

    const int c  = blockIdx.x, bh = blockIdx.y;
    const int tid = threadIdx.x, tx = tid & 15, ty = tid >> 4;

    const float* qp  = g_q   + ((size_t)bh*SS + (size_t)c*CH)*DH;
    const float* kp  = g_k   + ((size_t)bh*SS + (size_t)c*CH)*DH;
    const float* vp  = g_v   + ((size_t)bh*SS + (size_t)c*CH)*DH;
    const float* kvp = g_pkv + ((size_t)bh*NC + c)*DH*DH;
    const float* ksp = g_pks + ((size_t)bh*NC + c)*DH;

    for (int idx = tid; idx < 1024; idx += 256) {
        int r = idx >> 4, c4 = (idx & 15) << 2;
        float4 q4 = *(const float4*)(qp + r*DH + c4);
        *(float4*)&sQ[r*68 + c4] = q4;
        float4 k4 = *(const float4*)(kp + r*DH + c4);
        sB[(c4+0)*68 + r] = k4.x;
        sB[(c4+1)*68 + r] = k4.y;
        sB[(c4+2)*68 + r] = k4.z;
        sB[(c4+3)*68 + r] = k4.w;
    }
    if (tid < DH) sKs[tid] = ksp[tid];
    __syncthreads();

    {
        float acc[4][4] = {};
#pragma unroll 4
        for (int e = 0; e < DH; e++) {
            float a[4];
#pragma unroll
            for (int i=0;i<4;i++) a[i] = sQ[((ty<<2)+i)*68 + e];
            float4 b4 = *(const float4*)&sB[e*68 + (tx<<2)];
            float b[4] = {b4.x,b4.y,b4.z,b4.w};
#pragma unroll
            for (int i=0;i<4;i++)
#pragma unroll
                for (int j=0;j<4;j++) acc[i][j] = fmaf(a[i], b[j], acc[i][j]);
        }
        const int tb = ty<<2, sb = tx<<2;
#pragma unroll
        for (int i=0;i<4;i++)
#pragma unroll
            for (int j=0;j<4;j++)
                sS[(tb+i)*68 + sb+j] = (sb+j <= tb+i) ? acc[i][j] : 0.f;
    }
    __syncthreads();

    if (tid < DH) {
        float d = 0.f;
        for (int s = 0; s < CH; s++) d += sS[tid*68 + s];
        for (int e = 0; e < DH; e++) d += sQ[tid*68 + e] * sKs[e];
        sDen[tid] = d;
    }
    for (int idx = tid; idx < 1024; idx += 256) {
        int r = idx >> 4, c4 = (idx & 15) << 2;
        *(float4*)&sB[r*68 + c4] = *(const float4*)(vp  + r*DH + c4);
        *(float4*)&sC[r*68 + c4] = *(const float4*)(kvp + r*DH + c4);
    }
    __syncthreads();

    float acc[4][4] = {};
#pragma unroll 4
    for (int s = 0; s < CH; s++) {
        float a[4];
#pragma unroll
        for (int i=0;i<4;i++) a[i] = sS[((ty<<2)+i)*68 + s];
        float4 b4 = *(const float4*)&sB[s*68 + (tx<<2)];
        float b[4] = {b4.x,b4.y,b4.z,b4.w};
#pragma unroll
        for (int i=0;i<4;i++)
#pragma unroll
            for (int j=0;j<4;j++) acc[i][j] = fmaf(a[i], b[j], acc[i][j]);
    }
#pragma unroll 4
    for (int e = 0; e < DH; e++) {
        float a[4];
#pragma unroll
        for (int i=0;i<4;i++) a[i] = sQ[((ty<<2)+i)*68 + e];
        float4 b4 = *(const float4*)&sC[e*68 + (tx<<2)];
        float b[4] = {b4.x,b4.y,b4.z,b4.w};
#pragma unroll
        for (int i=0;i<4;i++)
#pragma unroll
            for (int j=0;j<4;j++) acc[i][j] = fmaf(a[i], b[j], acc[i][j]);
    }
    const int b_ = bh >> 3, h = bh & 7;
#pragma unroll
    for (int i=0;i<4;i++) {
        int t = (ty<<2) + i;
        float inv = 1.f / sDen[t];
        int sg = c*CH + t;
        float4 o = {acc[i][0]*inv, acc[i][1]*inv, acc[i][2]*inv, acc[i][3]*inv};
        *(float4*)(g_ctx + ((size_t)(b_*SS + sg))*DM + h*DH + (tx<<2)) = o;
    }
}

// ---------------------------------------------------------------------------
extern "C" void kernel_launch(void* const* d_in, const int* in_sizes, int n_in,
                              void* d_out, int out_size)
{
    const float* x   = (const float*)d_in[0];
    const float* Wqk = (const float*)d_in[1];
    const float* bqk = (const float*)d_in[2];
    const float* Wv  = (const float*)d_in[3];
    const float* bv  = (const float*)d_in[4];
    const float* Wo  = (const float*)d_in[5];
    const float* bo  = (const float*)d_in[6];
    float* out = (float*)d_out;

    cudaFuncSetAttribute(ctx_kernel,
        cudaFuncAttributeMaxDynamicSharedMemorySize, CTX_SMEM_BYTES);
    cudaFuncSetAttribute(gemm_tf32<0>,
        cudaFuncAttributeMaxDynamicSharedMemorySize, GEMM_SMEM_BYTES);
    cudaFuncSetAttribute(gemm_tf32<1>,
        cudaFuncAttributeMaxDynamicSharedMemorySize, GEMM_SMEM_BYTES);

    // proj: 1536 x 4096, K=512
    gemm_tf32<0><<<dim3(12, 32), 256, GEMM_SMEM_BYTES>>>(x, Wqk, Wv, bqk, bv, nullptr);
    chunkkv_kernel<<<dim3(NC, BH), 256>>>();
    scan_kernel<<<BH, 256>>>();
    ctx_kernel<<<dim3(NC, BH), 256, CTX_SMEM_BYTES>>>();
    // out: 512 x 4096, K=512
    gemm_tf32<1><<<dim3(4, 32), 256, GEMM_SMEM_BYTES>>>(nullptr, Wo, nullptr, bo, nullptr, out);
}

// round 6
// speedup vs baseline: 3.0862x; 1.9570x over previous
#include <cuda_runtime.h>
#include <math.h>
#include <stdint.h>

// Problem constants
#define BB 2
#define SS 2048
#define DM 512
#define HH 8
#define DH 64
#define CH 64               // chunk length for linear-attention scan
#define NC (SS/CH)          // 32 chunks
#define BH (BB*HH)          // 16 (b,h) pairs

// Scratch (device globals — no allocation allowed)
__device__ float g_q  [BH*SS*DH];      // [b,h,s,d]  elu+1 applied
__device__ float g_k  [BH*SS*DH];
__device__ float g_v  [BH*SS*DH];
__device__ float g_ckv[BH*NC*DH*DH];   // per-chunk  K^T V
__device__ float g_cks[BH*NC*DH];      // per-chunk  sum_s k
__device__ float g_pkv[BH*NC*DH*DH];   // exclusive prefix of g_ckv
__device__ float g_pks[BH*NC*DH];
__device__ float g_ctx[BB*SS*DM];      // context (tf32-rounded at store)
__device__ float g_xr [BB*SS*DM];      // x, tf32-rounded
__device__ float g_w  [3*DM*DM];       // [Wqk(1024 rows) ; Wv(512 rows)], tf32
__device__ float g_wor[DM*DM];         // Wo, tf32

// ===========================================================================
// helpers
// ===========================================================================
__device__ __forceinline__ uint32_t smem_u32(const void* p) {
    uint32_t a;
    asm("{ .reg .u64 t; cvta.to.shared.u64 t, %1; cvt.u32.u64 %0, t; }"
        : "=r"(a) : "l"(p));
    return a;
}
__device__ __forceinline__ uint32_t f2tf32(float f) {
    uint32_t u;
    asm("cvt.rna.tf32.f32 %0, %1;" : "=r"(u) : "f"(f));
    return u;
}
__device__ __forceinline__ float rtf(float f) { return __uint_as_float(f2tf32(f)); }

__device__ __forceinline__ void ldsm_x4(uint32_t& r0, uint32_t& r1,
                                        uint32_t& r2, uint32_t& r3, uint32_t a) {
    asm volatile("ldmatrix.sync.aligned.m8n8.x4.shared.b16 {%0,%1,%2,%3}, [%4];"
                 : "=r"(r0), "=r"(r1), "=r"(r2), "=r"(r3) : "r"(a));
}
__device__ __forceinline__ void ldsm_x2(uint32_t& r0, uint32_t& r1, uint32_t a) {
    asm volatile("ldmatrix.sync.aligned.m8n8.x2.shared.b16 {%0,%1}, [%2];"
                 : "=r"(r0), "=r"(r1) : "r"(a));
}
__device__ __forceinline__ void mma_tf32(float& c0, float& c1, float& c2, float& c3,
                                         uint32_t a0, uint32_t a1, uint32_t a2, uint32_t a3,
                                         uint32_t b0, uint32_t b1) {
    asm volatile("mma.sync.aligned.m16n8k8.row.col.f32.tf32.tf32.f32 "
                 "{%0,%1,%2,%3}, {%4,%5,%6,%7}, {%8,%9}, {%0,%1,%2,%3};"
                 : "+f"(c0), "+f"(c1), "+f"(c2), "+f"(c3)
                 : "r"(a0), "r"(a1), "r"(a2), "r"(a3), "r"(b0), "r"(b1));
}
#define CP16(dst, src) \
    asm volatile("cp.async.cg.shared.global [%0], [%1], 16;" \
                 :: "r"(dst), "l"(src) : "memory")
#define CP_COMMIT() asm volatile("cp.async.commit_group;" ::: "memory")
#define CP_WAIT1()  asm volatile("cp.async.wait_group 1;" ::: "memory")

// ===========================================================================
// Kernel 0: tf32-round inputs into scratch.
// ===========================================================================
__global__ __launch_bounds__(256) void round_kernel(
    const float* __restrict__ x, const float* __restrict__ Wqk,
    const float* __restrict__ Wv, const float* __restrict__ Wo)
{
    const int tid = blockIdx.x * 256 + threadIdx.x;
    const int stride = gridDim.x * 256;
    const float4* x4 = (const float4*)x;
    float4* o4 = (float4*)g_xr;
    for (int i = tid; i < BB*SS*DM/4; i += stride) {
        float4 v = x4[i];
        o4[i] = make_float4(rtf(v.x), rtf(v.y), rtf(v.z), rtf(v.w));
    }
    const float4* w4 = (const float4*)Wqk;
    float4* g4 = (float4*)g_w;
    for (int i = tid; i < 2*DM*DM/4; i += stride) {
        float4 v = w4[i];
        g4[i] = make_float4(rtf(v.x), rtf(v.y), rtf(v.z), rtf(v.w));
    }
    const float4* v4 = (const float4*)Wv;
    float4* h4 = (float4*)(g_w + 2*DM*DM);
    for (int i = tid; i < DM*DM/4; i += stride) {
        float4 v = v4[i];
        h4[i] = make_float4(rtf(v.x), rtf(v.y), rtf(v.z), rtf(v.w));
    }
    const float4* q4 = (const float4*)Wo;
    float4* k4 = (float4*)g_wor;
    for (int i = tid; i < DM*DM/4; i += stride) {
        float4 v = q4[i];
        k4[i] = make_float4(rtf(v.x), rtf(v.y), rtf(v.z), rtf(v.w));
    }
}

// ===========================================================================
// tf32 mma.sync GEMM, cp.async 3-stage pipeline.
// C[128x128] = A[128xK] * B[128xK]^T (NT), K=512, BK=32.
// 256 threads = 8 warps (2M x 4N), warp tile 64x32, frags m16n8k8.
// smem rows padded to 36 floats (144 B) -> conflict-free ldmatrix.
// MODE 0: proj (A=g_xr, B=g_w, epilogue bias+elu, scatter q/k/v)
// MODE 1: out  (A=g_ctx, B=g_wor, epilogue bias, store out)
// ===========================================================================
#define BK 32
#define LDAPAD 36
#define TILEB (128*LDAPAD*4)               // 18432
#define STAGEB (2*TILEB)                   // 36864
#define NSTAGE 3
#define GEMM_SMEM_BYTES (NSTAGE*STAGEB)    // 110592

template<int MODE>
__global__ __launch_bounds__(256) void gemm_tf32(
    const float* __restrict__ bias0, const float* __restrict__ bias1,
    float* __restrict__ outp)
{
    extern __shared__ __align__(16) char smem[];
    const int tid = threadIdx.x;
    const int wid = tid >> 5, lane = tid & 31;
    const int wm = wid & 1, wn = wid >> 1;          // 2 x 4 warp grid
    const int jt = blockIdx.x * 128;
    const int nt = blockIdx.y * 128;

    const float* Ap = (MODE == 1) ? (const float*)g_ctx : (const float*)g_xr;
    const float* Bp = (MODE == 1) ? (const float*)g_wor : (const float*)g_w;

    const uint32_t sb = smem_u32(smem);

    // per-thread gmem rows + smem dst offsets (4 x 16B for A, 4 for B)
    const float* rowA[4]; const float* rowB[4]; uint32_t dA[4], dB[4];
#pragma unroll
    for (int u = 0; u < 4; u++) {
        int idx = tid + u * 256;            // 0..1023
        int r = idx >> 3, c4 = idx & 7;     // row 0..127, 16B col 0..7
        dA[u] = (uint32_t)(r * (LDAPAD*4) + c4 * 16);
        dB[u] = dA[u] + TILEB;
        rowA[u] = Ap + (size_t)(nt + r) * DM + c4 * 4;
        rowB[u] = Bp + (size_t)(jt + r) * DM + c4 * 4;
    }

    // ldmatrix lane offsets
    const int g = lane >> 3, r8 = lane & 7;
    const uint32_t aoff = (uint32_t)((((g & 1) * 8 + r8) * LDAPAD + (g >> 1) * 4) * 4)
                        + (uint32_t)(wm * 64 * LDAPAD * 4);
    const uint32_t boff = (uint32_t)(((lane & 7) * LDAPAD + ((lane >> 3) & 1) * 4) * 4)
                        + (uint32_t)(wn * 32 * LDAPAD * 4) + TILEB;

    float acc[4][4][4] = {};   // [mf][nf][c]

    // prologue: stages 0,1
#pragma unroll
    for (int s = 0; s < 2; s++) {
        const uint32_t st = sb + s * STAGEB;
        const int k0 = s * BK;
#pragma unroll
        for (int u = 0; u < 4; u++) {
            CP16(st + dA[u], rowA[u] + k0);
            CP16(st + dB[u], rowB[u] + k0);
        }
        CP_COMMIT();
    }

    for (int it = 0; it < 16; it++) {
        const int buf = it % NSTAGE;
        CP_WAIT1();
        __syncthreads();
        const uint32_t abase = sb + buf * STAGEB + aoff;
        const uint32_t bbase = sb + buf * STAGEB + boff;
#pragma unroll
        for (int kk = 0; kk < 4; kk++) {
            uint32_t afr[4][4], bfr[4][2];
#pragma unroll
            for (int mf = 0; mf < 4; mf++)
                ldsm_x4(afr[mf][0], afr[mf][1], afr[mf][2], afr[mf][3],
                        abase + (uint32_t)(mf * 16 * LDAPAD * 4) + kk * 32);
#pragma unroll
            for (int nf = 0; nf < 4; nf++)
                ldsm_x2(bfr[nf][0], bfr[nf][1],
                        bbase + (uint32_t)(nf * 8 * LDAPAD * 4) + kk * 32);
#pragma unroll
            for (int mf = 0; mf < 4; mf++)
#pragma unroll
                for (int nf = 0; nf < 4; nf++)
                    mma_tf32(acc[mf][nf][0], acc[mf][nf][1],
                             acc[mf][nf][2], acc[mf][nf][3],
                             afr[mf][0], afr[mf][1], afr[mf][2], afr[mf][3],
                             bfr[nf][0], bfr[nf][1]);
        }
        __syncthreads();
        const int nxt = it + 2;
        if (nxt < 16) {
            const uint32_t st = sb + (nxt % NSTAGE) * STAGEB;
            const int k0 = nxt * BK;
#pragma unroll
            for (int u = 0; u < 4; u++) {
                CP16(st + dA[u], rowA[u] + k0);
                CP16(st + dB[u], rowB[u] + k0);
            }
        }
        CP_COMMIT();
    }

    // Epilogue. c0,c1 -> (row l/4, cols 2(l%4)+{0,1}); c2,c3 -> row+8
    const int rl = lane >> 2, cl = (lane & 3) * 2;
#pragma unroll
    for (int mf = 0; mf < 4; mf++) {
#pragma unroll
        for (int nf = 0; nf < 4; nf++) {
            const int j0 = jt + wn * 32 + nf * 8 + cl;
#pragma unroll
            for (int half = 0; half < 2; half++) {
                const int row = nt + wm * 64 + mf * 16 + rl + half * 8;
                float v0 = acc[mf][nf][half * 2 + 0];
                float v1 = acc[mf][nf][half * 2 + 1];
                if (MODE == 0) {
                    const int b_ = row >> 11, s_ = row & (SS - 1);
                    if (j0 < 2 * DM) {
                        v0 += bias0[j0]; v1 += bias0[j0 + 1];
                        v0 = (v0 > 0.f) ? v0 + 1.f : expf(v0);
                        v1 = (v1 > 0.f) ? v1 + 1.f : expf(v1);
                        int jm = j0 & (DM - 1);
                        int h = jm >> 6, d = jm & 63;
                        float* dst = (j0 < DM ? g_q : g_k)
                                   + (((size_t)(b_ * HH + h) * SS + s_) * DH + d);
                        *(float2*)dst = make_float2(v0, v1);
                    } else {
                        int jm = j0 - 2 * DM;
                        v0 += bias1[jm]; v1 += bias1[jm + 1];
                        int h = jm >> 6, d = jm & 63;
                        float* dst = g_v + (((size_t)(b_ * HH + h) * SS + s_) * DH + d);
                        *(float2*)dst = make_float2(v0, v1);
                    }
                } else {
                    float2 bi = *(const float2*)(bias0 + j0);
                    *(float2*)(outp + (size_t)row * DM + j0) =
                        make_float2(v0 + bi.x, v1 + bi.y);
                }
            }
        }
    }
}

// ---------------------------------------------------------------------------
// Kernel 2: per-chunk state  KV[d1][d2] = sum_s k[s][d1] v[s][d2], ksum[d].
// ---------------------------------------------------------------------------
__global__ __launch_bounds__(256) void chunkkv_kernel()
{
    __shared__ float sK[CH][68];
    __shared__ float sV[CH][68];
    const int c  = blockIdx.x, bh = blockIdx.y;
    const int tid = threadIdx.x;
    const int tx = tid & 15, ty = tid >> 4;
    const float* kp = g_k + ((size_t)bh*SS + (size_t)c*CH)*DH;
    const float* vp = g_v + ((size_t)bh*SS + (size_t)c*CH)*DH;
    for (int idx = tid; idx < CH*16; idx += 256) {
        int r = idx >> 4, c4 = (idx & 15) << 2;
        *(float4*)&sK[r][c4] = *(const float4*)(kp + r*DH + c4);
        *(float4*)&sV[r][c4] = *(const float4*)(vp + r*DH + c4);
    }
    __syncthreads();
    float acc[4][4] = {};
#pragma unroll 4
    for (int s = 0; s < CH; s++) {
        float a[4];
#pragma unroll
        for (int i=0;i<4;i++) a[i] = sK[s][(ty<<2)+i];
        float4 b4 = *(const float4*)&sV[s][tx<<2];
        float b[4] = {b4.x,b4.y,b4.z,b4.w};
#pragma unroll
        for (int i=0;i<4;i++)
#pragma unroll
            for (int j=0;j<4;j++) acc[i][j] = fmaf(a[i], b[j], acc[i][j]);
    }
    float* dst = g_ckv + ((size_t)bh*NC + c)*DH*DH;
#pragma unroll
    for (int i=0;i<4;i++) {
        float4 o = {acc[i][0],acc[i][1],acc[i][2],acc[i][3]};
        *(float4*)(dst + (size_t)((ty<<2)+i)*DH + (tx<<2)) = o;
    }
    if (tid < DH) {
        float s = 0.f;
        for (int r = 0; r < CH; r++) s += sK[r][tid];
        g_cks[((size_t)bh*NC + c)*DH + tid] = s;
    }
}

// ---------------------------------------------------------------------------
// Kernel 3: exclusive prefix scan over chunks. grid (BH, 4), float4/thread.
// ---------------------------------------------------------------------------
__global__ __launch_bounds__(256) void scan_kernel()
{
    const int bh = blockIdx.x;
    const int tid = threadIdx.x;
    const size_t base = (size_t)bh * NC;
    const int e4 = blockIdx.y * 256 + tid;      // float4 index, 0..1023
    const float4* src = (const float4*)g_ckv;
    float4* dst = (float4*)g_pkv;
    float4 run = make_float4(0.f, 0.f, 0.f, 0.f);
#pragma unroll 8
    for (int c = 0; c < NC; c++) {
        size_t o = (base + c) * (DH*DH/4) + e4;
        float4 v = src[o];
        dst[o] = run;
        run.x += v.x; run.y += v.y; run.z += v.z; run.w += v.w;
    }
    if (blockIdx.y == 0 && tid < DH) {
        float r = 0.f;
#pragma unroll 8
        for (int c = 0; c < NC; c++) {
            size_t o = (base + c)*DH + tid;
            g_pks[o] = r;
            r += g_cks[o];
        }
    }
}

// ---------------------------------------------------------------------------
// Kernel 4: per-chunk context. (stores g_ctx tf32-rounded for out-GEMM)
// ---------------------------------------------------------------------------
#define CTX_SMEM_BYTES ((4*64*68 + 128) * 4)

__global__ __launch_bounds__(256) void ctx_kernel()
{
    extern __shared__ float sm[];
    float* sQ   = sm;                 // [64][68] natural [t][e]
    float* sB   = sm + 64*68;         // phase1: k^T [e][s]; phase2: v [s][d]
    float* sS   = sm + 2*64*68;       // [t][s]
    float* sC   = sm + 3*64*68;       // KV_pre [e][d]
    float* sKs  = sm + 4*64*68;       // [64]
    float* sDen = sKs + 64;           // [64]

    const int c  = blockIdx.x, bh = blockIdx.y;
    const int tid = threadIdx.x, tx = tid & 15, ty = tid >> 4;

    const float* qp  = g_q   + ((size_t)bh*SS + (size_t)c*CH)*DH;
    const float* kp  = g_k   + ((size_t)bh*SS + (size_t)c*CH)*DH;
    const float* vp  = g_v   + ((size_t)bh*SS + (size_t)c*CH)*DH;
    const float* kvp = g_pkv + ((size_t)bh*NC + c)*DH*DH;
    const float* ksp = g_pks + ((size_t)bh*NC + c)*DH;

    for (int idx = tid; idx < 1024; idx += 256) {
        int r = idx >> 4, c4 = (idx & 15) << 2;
        float4 q4 = *(const float4*)(qp + r*DH + c4);
        *(float4*)&sQ[r*68 + c4] = q4;
        float4 k4 = *(const float4*)(kp + r*DH + c4);
        sB[(c4+0)*68 + r] = k4.x;
        sB[(c4+1)*68 + r] = k4.y;
        sB[(c4+2)*68 + r] = k4.z;
        sB[(c4+3)*68 + r] = k4.w;
    }
    if (tid < DH) sKs[tid] = ksp[tid];
    __syncthreads();

    {
        float acc[4][4] = {};
#pragma unroll 4
        for (int e = 0; e < DH; e++) {
            float a[4];
#pragma unroll
            for (int i=0;i<4;i++) a[i] = sQ[((ty<<2)+i)*68 + e];
            float4 b4 = *(const float4*)&sB[e*68 + (tx<<2)];
            float b[4] = {b4.x,b4.y,b4.z,b4.w};
#pragma unroll
            for (int i=0;i<4;i++)
#pragma unroll
                for (int j=0;j<4;j++) acc[i][j] = fmaf(a[i], b[j], acc[i][j]);
        }
        const int tb = ty<<2, sb = tx<<2;
#pragma unroll
        for (int i=0;i<4;i++)
#pragma unroll
            for (int j=0;j<4;j++)
                sS[(tb+i)*68 + sb+j] = (sb+j <= tb+i) ? acc[i][j] : 0.f;
    }
    __syncthreads();

    if (tid < DH) {
        float d = 0.f;
        for (int s = 0; s < CH; s++) d += sS[tid*68 + s];
        for (int e = 0; e < DH; e++) d += sQ[tid*68 + e] * sKs[e];
        sDen[tid] = d;
    }
    for (int idx = tid; idx < 1024; idx += 256) {
        int r = idx >> 4, c4 = (idx & 15) << 2;
        *(float4*)&sB[r*68 + c4] = *(const float4*)(vp  + r*DH + c4);
        *(float4*)&sC[r*68 + c4] = *(const float4*)(kvp + r*DH + c4);
    }
    __syncthreads();

    float acc[4][4] = {};
#pragma unroll 4
    for (int s = 0; s < CH; s++) {
        float a[4];
#pragma unroll
        for (int i=0;i<4;i++) a[i] = sS[((ty<<2)+i)*68 + s];
        float4 b4 = *(const float4*)&sB[s*68 + (tx<<2)];
        float b[4] = {b4.x,b4.y,b4.z,b4.w};
#pragma unroll
        for (int i=0;i<4;i++)
#pragma unroll
            for (int j=0;j<4;j++) acc[i][j] = fmaf(a[i], b[j], acc[i][j]);
    }
#pragma unroll 4
    for (int e = 0; e < DH; e++) {
        float a[4];
#pragma unroll
        for (int i=0;i<4;i++) a[i] = sQ[((ty<<2)+i)*68 + e];
        float4 b4 = *(const float4*)&sC[e*68 + (tx<<2)];
        float b[4] = {b4.x,b4.y,b4.z,b4.w};
#pragma unroll
        for (int i=0;i<4;i++)
#pragma unroll
            for (int j=0;j<4;j++) acc[i][j] = fmaf(a[i], b[j], acc[i][j]);
    }
    const int b_ = bh >> 3, h = bh & 7;
#pragma unroll
    for (int i=0;i<4;i++) {
        int t = (ty<<2) + i;
        float inv = 1.f / sDen[t];
        int sg = c*CH + t;
        float4 o = {rtf(acc[i][0]*inv), rtf(acc[i][1]*inv),
                    rtf(acc[i][2]*inv), rtf(acc[i][3]*inv)};
        *(float4*)(g_ctx + ((size_t)(b_*SS + sg))*DM + h*DH + (tx<<2)) = o;
    }
}

// ---------------------------------------------------------------------------
extern "C" void kernel_launch(void* const* d_in, const int* in_sizes, int n_in,
                              void* d_out, int out_size)
{
    const float* x   = (const float*)d_in[0];
    const float* Wqk = (const float*)d_in[1];
    const float* bqk = (const float*)d_in[2];
    const float* Wv  = (const float*)d_in[3];
    const float* bv  = (const float*)d_in[4];
    const float* Wo  = (const float*)d_in[5];
    const float* bo  = (const float*)d_in[6];
    float* out = (float*)d_out;

    cudaFuncSetAttribute(ctx_kernel,
        cudaFuncAttributeMaxDynamicSharedMemorySize, CTX_SMEM_BYTES);
    cudaFuncSetAttribute(gemm_tf32<0>,
        cudaFuncAttributeMaxDynamicSharedMemorySize, GEMM_SMEM_BYTES);
    cudaFuncSetAttribute(gemm_tf32<1>,
        cudaFuncAttributeMaxDynamicSharedMemorySize, GEMM_SMEM_BYTES);

    round_kernel<<<768, 256>>>(x, Wqk, Wv, Wo);
    gemm_tf32<0><<<dim3(12, 32), 256, GEMM_SMEM_BYTES>>>(bqk, bv, nullptr);
    chunkkv_kernel<<<dim3(NC, BH), 256>>>();
    scan_kernel<<<dim3(BH, 4), 256>>>();
    ctx_kernel<<<dim3(NC, BH), 256, CTX_SMEM_BYTES>>>();
    gemm_tf32<1><<<dim3(4, 32), 256, GEMM_SMEM_BYTES>>>(bo, nullptr, out);
}

// round 7
// speedup vs baseline: 3.8708x; 1.2542x over previous
#include <cuda_runtime.h>
#include <math.h>
#include <stdint.h>

// Problem constants
#define BB 2
#define SS 2048
#define DM 512
#define HH 8
#define DH 64
#define CH 64               // chunk length for linear-attention scan
#define NC (SS/CH)          // 32 chunks
#define BH (BB*HH)          // 16 (b,h) pairs

// Scratch (device globals — no allocation allowed)
__device__ float g_q  [BH*SS*DH];      // [b,h,s,d]  elu+1, tf32-rounded
__device__ float g_k  [BH*SS*DH];      // tf32-rounded
__device__ float g_v  [BH*SS*DH];      // tf32-rounded
__device__ float g_ckv[BH*NC*DH*DH];   // per-chunk KV^T: [d2][d1] = KV[d1][d2]
__device__ float g_cks[BH*NC*DH];      // per-chunk  sum_s k
__device__ float g_pkv[BH*NC*DH*DH];   // exclusive prefix of g_ckv (still KV^T)
__device__ float g_pks[BH*NC*DH];
__device__ float g_ctx[BB*SS*DM];      // context (tf32-rounded at store)
__device__ float g_xr [BB*SS*DM];      // x, tf32-rounded
__device__ float g_w  [3*DM*DM];       // [Wqk(1024 rows) ; Wv(512 rows)], tf32
__device__ float g_wor[DM*DM];         // Wo, tf32

// ===========================================================================
// helpers
// ===========================================================================
__device__ __forceinline__ uint32_t smem_u32(const void* p) {
    uint32_t a;
    asm("{ .reg .u64 t; cvta.to.shared.u64 t, %1; cvt.u32.u64 %0, t; }"
        : "=r"(a) : "l"(p));
    return a;
}
__device__ __forceinline__ uint32_t f2tf32(float f) {
    uint32_t u;
    asm("cvt.rna.tf32.f32 %0, %1;" : "=r"(u) : "f"(f));
    return u;
}
__device__ __forceinline__ float rtf(float f) { return __uint_as_float(f2tf32(f)); }

__device__ __forceinline__ void ldsm_x4(uint32_t& r0, uint32_t& r1,
                                        uint32_t& r2, uint32_t& r3, uint32_t a) {
    asm volatile("ldmatrix.sync.aligned.m8n8.x4.shared.b16 {%0,%1,%2,%3}, [%4];"
                 : "=r"(r0), "=r"(r1), "=r"(r2), "=r"(r3) : "r"(a));
}
__device__ __forceinline__ void ldsm_x2(uint32_t& r0, uint32_t& r1, uint32_t a) {
    asm volatile("ldmatrix.sync.aligned.m8n8.x2.shared.b16 {%0,%1}, [%2];"
                 : "=r"(r0), "=r"(r1) : "r"(a));
}
__device__ __forceinline__ void mma_tf32(float& c0, float& c1, float& c2, float& c3,
                                         uint32_t a0, uint32_t a1, uint32_t a2, uint32_t a3,
                                         uint32_t b0, uint32_t b1) {
    asm volatile("mma.sync.aligned.m16n8k8.row.col.f32.tf32.tf32.f32 "
                 "{%0,%1,%2,%3}, {%4,%5,%6,%7}, {%8,%9}, {%0,%1,%2,%3};"
                 : "+f"(c0), "+f"(c1), "+f"(c2), "+f"(c3)
                 : "r"(a0), "r"(a1), "r"(a2), "r"(a3), "r"(b0), "r"(b1));
}
#define CP16(dst, src) \
    asm volatile("cp.async.cg.shared.global [%0], [%1], 16;" \
                 :: "r"(dst), "l"(src) : "memory")
#define CP_COMMIT() asm volatile("cp.async.commit_group;" ::: "memory")
#define CP_WAIT1()  asm volatile("cp.async.wait_group 1;" ::: "memory")

// 64-wide tiles: rows padded to 68 floats (272 B, 272 mod 128 = 16 -> no conflicts)
#define TP 68
#define TPB (TP*4)

// ===========================================================================
// Kernel 0: tf32-round inputs into scratch.
// ===========================================================================
__global__ __launch_bounds__(256) void round_kernel(
    const float* __restrict__ x, const float* __restrict__ Wqk,
    const float* __restrict__ Wv, const float* __restrict__ Wo)
{
    const int tid = blockIdx.x * 256 + threadIdx.x;
    const int stride = gridDim.x * 256;
    const float4* x4 = (const float4*)x;
    float4* o4 = (float4*)g_xr;
    for (int i = tid; i < BB*SS*DM/4; i += stride) {
        float4 v = x4[i];
        o4[i] = make_float4(rtf(v.x), rtf(v.y), rtf(v.z), rtf(v.w));
    }
    const float4* w4 = (const float4*)Wqk;
    float4* g4 = (float4*)g_w;
    for (int i = tid; i < 2*DM*DM/4; i += stride) {
        float4 v = w4[i];
        g4[i] = make_float4(rtf(v.x), rtf(v.y), rtf(v.z), rtf(v.w));
    }
    const float4* v4 = (const float4*)Wv;
    float4* h4 = (float4*)(g_w + 2*DM*DM);
    for (int i = tid; i < DM*DM/4; i += stride) {
        float4 v = v4[i];
        h4[i] = make_float4(rtf(v.x), rtf(v.y), rtf(v.z), rtf(v.w));
    }
    const float4* q4 = (const float4*)Wo;
    float4* k4 = (float4*)g_wor;
    for (int i = tid; i < DM*DM/4; i += stride) {
        float4 v = q4[i];
        k4[i] = make_float4(rtf(v.x), rtf(v.y), rtf(v.z), rtf(v.w));
    }
}

// ===========================================================================
// tf32 mma.sync GEMM, cp.async 3-stage pipeline (unchanged from R6 except
// proj epilogue stores tf32-rounded q/k/v).
// ===========================================================================
#define BK 32
#define LDAPAD 36
#define TILEB (128*LDAPAD*4)               // 18432
#define STAGEB (2*TILEB)                   // 36864
#define NSTAGE 3
#define GEMM_SMEM_BYTES (NSTAGE*STAGEB)    // 110592

template<int MODE>
__global__ __launch_bounds__(256) void gemm_tf32(
    const float* __restrict__ bias0, const float* __restrict__ bias1,
    float* __restrict__ outp)
{
    extern __shared__ __align__(16) char smem[];
    const int tid = threadIdx.x;
    const int wid = tid >> 5, lane = tid & 31;
    const int wm = wid & 1, wn = wid >> 1;          // 2 x 4 warp grid
    const int jt = blockIdx.x * 128;
    const int nt = blockIdx.y * 128;

    const float* Ap = (MODE == 1) ? (const float*)g_ctx : (const float*)g_xr;
    const float* Bp = (MODE == 1) ? (const float*)g_wor : (const float*)g_w;

    const uint32_t sb = smem_u32(smem);

    const float* rowA[4]; const float* rowB[4]; uint32_t dA[4], dB[4];
#pragma unroll
    for (int u = 0; u < 4; u++) {
        int idx = tid + u * 256;
        int r = idx >> 3, c4 = idx & 7;
        dA[u] = (uint32_t)(r * (LDAPAD*4) + c4 * 16);
        dB[u] = dA[u] + TILEB;
        rowA[u] = Ap + (size_t)(nt + r) * DM + c4 * 4;
        rowB[u] = Bp + (size_t)(jt + r) * DM + c4 * 4;
    }

    const int g = lane >> 3, r8 = lane & 7;
    const uint32_t aoff = (uint32_t)((((g & 1) * 8 + r8) * LDAPAD + (g >> 1) * 4) * 4)
                        + (uint32_t)(wm * 64 * LDAPAD * 4);
    const uint32_t boff = (uint32_t)(((lane & 7) * LDAPAD + ((lane >> 3) & 1) * 4) * 4)
                        + (uint32_t)(wn * 32 * LDAPAD * 4) + TILEB;

    float acc[4][4][4] = {};

#pragma unroll
    for (int s = 0; s < 2; s++) {
        const uint32_t st = sb + s * STAGEB;
        const int k0 = s * BK;
#pragma unroll
        for (int u = 0; u < 4; u++) {
            CP16(st + dA[u], rowA[u] + k0);
            CP16(st + dB[u], rowB[u] + k0);
        }
        CP_COMMIT();
    }

    for (int it = 0; it < 16; it++) {
        const int buf = it % NSTAGE;
        CP_WAIT1();
        __syncthreads();
        const uint32_t abase = sb + buf * STAGEB + aoff;
        const uint32_t bbase = sb + buf * STAGEB + boff;
#pragma unroll
        for (int kk = 0; kk < 4; kk++) {
            uint32_t afr[4][4], bfr[4][2];
#pragma unroll
            for (int mf = 0; mf < 4; mf++)
                ldsm_x4(afr[mf][0], afr[mf][1], afr[mf][2], afr[mf][3],
                        abase + (uint32_t)(mf * 16 * LDAPAD * 4) + kk * 32);
#pragma unroll
            for (int nf = 0; nf < 4; nf++)
                ldsm_x2(bfr[nf][0], bfr[nf][1],
                        bbase + (uint32_t)(nf * 8 * LDAPAD * 4) + kk * 32);
#pragma unroll
            for (int mf = 0; mf < 4; mf++)
#pragma unroll
                for (int nf = 0; nf < 4; nf++)
                    mma_tf32(acc[mf][nf][0], acc[mf][nf][1],
                             acc[mf][nf][2], acc[mf][nf][3],
                             afr[mf][0], afr[mf][1], afr[mf][2], afr[mf][3],
                             bfr[nf][0], bfr[nf][1]);
        }
        __syncthreads();
        const int nxt = it + 2;
        if (nxt < 16) {
            const uint32_t st = sb + (nxt % NSTAGE) * STAGEB;
            const int k0 = nxt * BK;
#pragma unroll
            for (int u = 0; u < 4; u++) {
                CP16(st + dA[u], rowA[u] + k0);
                CP16(st + dB[u], rowB[u] + k0);
            }
        }
        CP_COMMIT();
    }

    const int rl = lane >> 2, cl = (lane & 3) * 2;
#pragma unroll
    for (int mf = 0; mf < 4; mf++) {
#pragma unroll
        for (int nf = 0; nf < 4; nf++) {
            const int j0 = jt + wn * 32 + nf * 8 + cl;
#pragma unroll
            for (int half = 0; half < 2; half++) {
                const int row = nt + wm * 64 + mf * 16 + rl + half * 8;
                float v0 = acc[mf][nf][half * 2 + 0];
                float v1 = acc[mf][nf][half * 2 + 1];
                if (MODE == 0) {
                    const int b_ = row >> 11, s_ = row & (SS - 1);
                    if (j0 < 2 * DM) {
                        v0 += bias0[j0]; v1 += bias0[j0 + 1];
                        v0 = (v0 > 0.f) ? v0 + 1.f : expf(v0);
                        v1 = (v1 > 0.f) ? v1 + 1.f : expf(v1);
                        int jm = j0 & (DM - 1);
                        int h = jm >> 6, d = jm & 63;
                        float* dst = (j0 < DM ? g_q : g_k)
                                   + (((size_t)(b_ * HH + h) * SS + s_) * DH + d);
                        *(float2*)dst = make_float2(rtf(v0), rtf(v1));
                    } else {
                        int jm = j0 - 2 * DM;
                        v0 += bias1[jm]; v1 += bias1[jm + 1];
                        int h = jm >> 6, d = jm & 63;
                        float* dst = g_v + (((size_t)(b_ * HH + h) * SS + s_) * DH + d);
                        *(float2*)dst = make_float2(rtf(v0), rtf(v1));
                    }
                } else {
                    float2 bi = *(const float2*)(bias0 + j0);
                    *(float2*)(outp + (size_t)row * DM + j0) =
                        make_float2(v0 + bi.x, v1 + bi.y);
                }
            }
        }
    }
}

// ===========================================================================
// Kernel 2: per-chunk KV^T via mma.sync.
// C[d2][d1] = sum_s v[s][d2] k[s][d1]  (A = v^T, B = k^T, both [d][s]).
// 128 threads = 4 warps (2x2), warp tile 32x32.
// ===========================================================================
__global__ __launch_bounds__(128) void chunkkv_kernel()
{
    __shared__ float sKT[64*TP];
    __shared__ float sVT[64*TP];
    const int c  = blockIdx.x, bh = blockIdx.y;
    const int tid = threadIdx.x;
    const int wid = tid >> 5, lane = tid & 31;
    const int wm = wid & 1, wn = wid >> 1;
    const float* kp = g_k + ((size_t)bh*SS + (size_t)c*CH)*DH;
    const float* vp = g_v + ((size_t)bh*SS + (size_t)c*CH)*DH;

    // transpose-load k,v -> [d][s]
    for (int idx = tid; idx < 1024; idx += 128) {
        int r = idx >> 4, c4 = (idx & 15) << 2;
        float4 k4 = *(const float4*)(kp + r*DH + c4);
        sKT[(c4+0)*TP + r] = k4.x; sKT[(c4+1)*TP + r] = k4.y;
        sKT[(c4+2)*TP + r] = k4.z; sKT[(c4+3)*TP + r] = k4.w;
        float4 v4 = *(const float4*)(vp + r*DH + c4);
        sVT[(c4+0)*TP + r] = v4.x; sVT[(c4+1)*TP + r] = v4.y;
        sVT[(c4+2)*TP + r] = v4.z; sVT[(c4+3)*TP + r] = v4.w;
    }
    __syncthreads();

    const int g = lane >> 3, r8 = lane & 7;
    const uint32_t aoff = (uint32_t)((((g & 1) * 8 + r8) * TP + (g >> 1) * 4) * 4);
    const uint32_t boff = (uint32_t)(((lane & 7) * TP + ((lane >> 3) & 1) * 4) * 4);
    const uint32_t abase = smem_u32(sVT) + (uint32_t)(wm * 32 * TPB) + aoff;
    const uint32_t bbase = smem_u32(sKT) + (uint32_t)(wn * 32 * TPB) + boff;

    float acc[2][4][4] = {};
#pragma unroll
    for (int kk = 0; kk < 8; kk++) {
        uint32_t afr[2][4], bfr[4][2];
#pragma unroll
        for (int mf = 0; mf < 2; mf++)
            ldsm_x4(afr[mf][0], afr[mf][1], afr[mf][2], afr[mf][3],
                    abase + (uint32_t)(mf * 16 * TPB) + kk * 32);
#pragma unroll
        for (int nf = 0; nf < 4; nf++)
            ldsm_x2(bfr[nf][0], bfr[nf][1],
                    bbase + (uint32_t)(nf * 8 * TPB) + kk * 32);
#pragma unroll
        for (int mf = 0; mf < 2; mf++)
#pragma unroll
            for (int nf = 0; nf < 4; nf++)
                mma_tf32(acc[mf][nf][0], acc[mf][nf][1],
                         acc[mf][nf][2], acc[mf][nf][3],
                         afr[mf][0], afr[mf][1], afr[mf][2], afr[mf][3],
                         bfr[nf][0], bfr[nf][1]);
    }

    float* dst = g_ckv + ((size_t)bh*NC + c)*DH*DH;
    const int rl = lane >> 2, cl = (lane & 3) * 2;
#pragma unroll
    for (int mf = 0; mf < 2; mf++)
#pragma unroll
        for (int nf = 0; nf < 4; nf++)
#pragma unroll
            for (int half = 0; half < 2; half++) {
                int row = wm*32 + mf*16 + rl + half*8;   // d2
                int col = wn*32 + nf*8 + cl;             // d1
                *(float2*)(dst + row*DH + col) =
                    make_float2(acc[mf][nf][half*2], acc[mf][nf][half*2+1]);
            }

    if (tid < DH) {
        float s = 0.f;
#pragma unroll 8
        for (int r = 0; r < CH; r++) s += sKT[tid*TP + r];
        g_cks[((size_t)bh*NC + c)*DH + tid] = s;
    }
}

// ===========================================================================
// Kernel 3: exclusive prefix scan, batched loads (MLP=32). grid (BH,16)x256.
// ===========================================================================
__global__ __launch_bounds__(256) void scan_kernel()
{
    const int bh = blockIdx.x;
    const int tid = threadIdx.x;
    const int e = blockIdx.y * 256 + tid;       // 0..4095
    const size_t base = (size_t)bh * NC;
    float v[NC];
#pragma unroll
    for (int c = 0; c < NC; c++)
        v[c] = g_ckv[(base + c) * (DH*DH) + e];
    float run = 0.f;
#pragma unroll
    for (int c = 0; c < NC; c++) {
        g_pkv[(base + c) * (DH*DH) + e] = run;
        run += v[c];
    }
    if (blockIdx.y == 0 && tid < DH) {
        float w[NC];
#pragma unroll
        for (int c = 0; c < NC; c++) w[c] = g_cks[(base + c)*DH + tid];
        float r = 0.f;
#pragma unroll
        for (int c = 0; c < NC; c++) {
            g_pks[(base + c)*DH + tid] = r;
            r += w[c];
        }
    }
}

// ===========================================================================
// Kernel 4: per-chunk context via mma.sync.
//  S = q k^T (mask, rtf) ; den = rowsum(S) + q.ks_pre
//  ctx = (S @ v + q @ KV_pre) / den   (B-operands: k natural, v^T, KV^T)
// 128 threads = 4 warps (2x2), warp tile 32x32. Dynamic smem 5 tiles.
// ===========================================================================
#define CTX_SMEM_BYTES ((5*64*TP + 128) * 4)

__global__ __launch_bounds__(128) void ctx_kernel()
{
    extern __shared__ float sm[];
    float* sQ   = sm;                 // [t][e]
    float* sK   = sm + 64*TP;         // [s][e]
    float* sS   = sm + 2*64*TP;       // [t][s] masked, tf32
    float* sVT  = sm + 3*64*TP;       // [d][s]
    float* sKVT = sm + 4*64*TP;       // [d][e]  (= g_pkv rows)
    float* sKs  = sm + 5*64*TP;       // [64]
    float* sDen = sKs + 64;           // [64]

    const int c  = blockIdx.x, bh = blockIdx.y;
    const int tid = threadIdx.x;
    const int wid = tid >> 5, lane = tid & 31;
    const int wm = wid & 1, wn = wid >> 1;

    const float* qp  = g_q   + ((size_t)bh*SS + (size_t)c*CH)*DH;
    const float* kp  = g_k   + ((size_t)bh*SS + (size_t)c*CH)*DH;
    const float* vp  = g_v   + ((size_t)bh*SS + (size_t)c*CH)*DH;
    const float* kvp = g_pkv + ((size_t)bh*NC + c)*DH*DH;
    const float* ksp = g_pks + ((size_t)bh*NC + c)*DH;

    for (int idx = tid; idx < 1024; idx += 128) {
        int r = idx >> 4, c4 = (idx & 15) << 2;
        *(float4*)&sQ[r*TP + c4]   = *(const float4*)(qp + r*DH + c4);
        *(float4*)&sK[r*TP + c4]   = *(const float4*)(kp + r*DH + c4);
        *(float4*)&sKVT[r*TP + c4] = *(const float4*)(kvp + r*DH + c4);
        float4 v4 = *(const float4*)(vp + r*DH + c4);
        sVT[(c4+0)*TP + r] = v4.x; sVT[(c4+1)*TP + r] = v4.y;
        sVT[(c4+2)*TP + r] = v4.z; sVT[(c4+3)*TP + r] = v4.w;
    }
    if (tid < DH) sKs[tid] = ksp[tid];
    __syncthreads();

    const int g = lane >> 3, r8 = lane & 7;
    const uint32_t aoff = (uint32_t)((((g & 1) * 8 + r8) * TP + (g >> 1) * 4) * 4);
    const uint32_t boff = (uint32_t)(((lane & 7) * TP + ((lane >> 3) & 1) * 4) * 4);
    const uint32_t awm = (uint32_t)(wm * 32 * TPB);
    const uint32_t bwn = (uint32_t)(wn * 32 * TPB);
    const int rl = lane >> 2, cl = (lane & 3) * 2;

    // ---- mma1: S = q . k^T ----
    {
        const uint32_t abase = smem_u32(sQ) + awm + aoff;
        const uint32_t bbase = smem_u32(sK) + bwn + boff;
        float acc[2][4][4] = {};
#pragma unroll
        for (int kk = 0; kk < 8; kk++) {
            uint32_t afr[2][4], bfr[4][2];
#pragma unroll
            for (int mf = 0; mf < 2; mf++)
                ldsm_x4(afr[mf][0], afr[mf][1], afr[mf][2], afr[mf][3],
                        abase + (uint32_t)(mf * 16 * TPB) + kk * 32);
#pragma unroll
            for (int nf = 0; nf < 4; nf++)
                ldsm_x2(bfr[nf][0], bfr[nf][1],
                        bbase + (uint32_t)(nf * 8 * TPB) + kk * 32);
#pragma unroll
            for (int mf = 0; mf < 2; mf++)
#pragma unroll
                for (int nf = 0; nf < 4; nf++)
                    mma_tf32(acc[mf][nf][0], acc[mf][nf][1],
                             acc[mf][nf][2], acc[mf][nf][3],
                             afr[mf][0], afr[mf][1], afr[mf][2], afr[mf][3],
                             bfr[nf][0], bfr[nf][1]);
        }
        // mask (tril) + rtf + store to sS
#pragma unroll
        for (int mf = 0; mf < 2; mf++)
#pragma unroll
            for (int nf = 0; nf < 4; nf++)
#pragma unroll
                for (int half = 0; half < 2; half++) {
                    int t = wm*32 + mf*16 + rl + half*8;
                    int s = wn*32 + nf*8 + cl;
                    float v0 = (s   <= t) ? rtf(acc[mf][nf][half*2])   : 0.f;
                    float v1 = (s+1 <= t) ? rtf(acc[mf][nf][half*2+1]) : 0.f;
                    *(float2*)&sS[t*TP + s] = make_float2(v0, v1);
                }
    }
    __syncthreads();

    // den (fp32)
    if (tid < DH) {
        float d = 0.f;
#pragma unroll 8
        for (int s = 0; s < CH; s++) d += sS[tid*TP + s];
#pragma unroll 8
        for (int e = 0; e < DH; e++) d += sQ[tid*TP + e] * sKs[e];
        sDen[tid] = d;
    }

    // ---- mma2+3: ctx = S @ v + q @ KV_pre ----
    float acc[2][4][4] = {};
    {
        const uint32_t a1 = smem_u32(sS) + awm + aoff;
        const uint32_t b1 = smem_u32(sVT) + bwn + boff;
#pragma unroll
        for (int kk = 0; kk < 8; kk++) {
            uint32_t afr[2][4], bfr[4][2];
#pragma unroll
            for (int mf = 0; mf < 2; mf++)
                ldsm_x4(afr[mf][0], afr[mf][1], afr[mf][2], afr[mf][3],
                        a1 + (uint32_t)(mf * 16 * TPB) + kk * 32);
#pragma unroll
            for (int nf = 0; nf < 4; nf++)
                ldsm_x2(bfr[nf][0], bfr[nf][1],
                        b1 + (uint32_t)(nf * 8 * TPB) + kk * 32);
#pragma unroll
            for (int mf = 0; mf < 2; mf++)
#pragma unroll
                for (int nf = 0; nf < 4; nf++)
                    mma_tf32(acc[mf][nf][0], acc[mf][nf][1],
                             acc[mf][nf][2], acc[mf][nf][3],
                             afr[mf][0], afr[mf][1], afr[mf][2], afr[mf][3],
                             bfr[nf][0], bfr[nf][1]);
        }
        const uint32_t a2 = smem_u32(sQ) + awm + aoff;
        const uint32_t b2 = smem_u32(sKVT) + bwn + boff;
#pragma unroll
        for (int kk = 0; kk < 8; kk++) {
            uint32_t afr[2][4], bfr[4][2];
#pragma unroll
            for (int mf = 0; mf < 2; mf++)
                ldsm_x4(afr[mf][0], afr[mf][1], afr[mf][2], afr[mf][3],
                        a2 + (uint32_t)(mf * 16 * TPB) + kk * 32);
#pragma unroll
            for (int nf = 0; nf < 4; nf++)
                ldsm_x2(bfr[nf][0], bfr[nf][1],
                        b2 + (uint32_t)(nf * 8 * TPB) + kk * 32);
#pragma unroll
            for (int mf = 0; mf < 2; mf++)
#pragma unroll
                for (int nf = 0; nf < 4; nf++)
                    mma_tf32(acc[mf][nf][0], acc[mf][nf][1],
                             acc[mf][nf][2], acc[mf][nf][3],
                             afr[mf][0], afr[mf][1], afr[mf][2], afr[mf][3],
                             bfr[nf][0], bfr[nf][1]);
        }
    }
    __syncthreads();   // sDen visibility

    const int b_ = bh >> 3, h = bh & 7;
#pragma unroll
    for (int mf = 0; mf < 2; mf++)
#pragma unroll
        for (int nf = 0; nf < 4; nf++)
#pragma unroll
            for (int half = 0; half < 2; half++) {
                int t = wm*32 + mf*16 + rl + half*8;
                int d = wn*32 + nf*8 + cl;
                float inv = 1.f / sDen[t];
                int sg = c*CH + t;
                float v0 = rtf(acc[mf][nf][half*2]   * inv);
                float v1 = rtf(acc[mf][nf][half*2+1] * inv);
                *(float2*)(g_ctx + ((size_t)(b_*SS + sg))*DM + h*DH + d) =
                    make_float2(v0, v1);
            }
}

// ---------------------------------------------------------------------------
extern "C" void kernel_launch(void* const* d_in, const int* in_sizes, int n_in,
                              void* d_out, int out_size)
{
    const float* x   = (const float*)d_in[0];
    const float* Wqk = (const float*)d_in[1];
    const float* bqk = (const float*)d_in[2];
    const float* Wv  = (const float*)d_in[3];
    const float* bv  = (const float*)d_in[4];
    const float* Wo  = (const float*)d_in[5];
    const float* bo  = (const float*)d_in[6];
    float* out = (float*)d_out;

    cudaFuncSetAttribute(ctx_kernel,
        cudaFuncAttributeMaxDynamicSharedMemorySize, CTX_SMEM_BYTES);
    cudaFuncSetAttribute(gemm_tf32<0>,
        cudaFuncAttributeMaxDynamicSharedMemorySize, GEMM_SMEM_BYTES);
    cudaFuncSetAttribute(gemm_tf32<1>,
        cudaFuncAttributeMaxDynamicSharedMemorySize, GEMM_SMEM_BYTES);

    round_kernel<<<768, 256>>>(x, Wqk, Wv, Wo);
    gemm_tf32<0><<<dim3(12, 32), 256, GEMM_SMEM_BYTES>>>(bqk, bv, nullptr);
    chunkkv_kernel<<<dim3(NC, BH), 128>>>();
    scan_kernel<<<dim3(BH, 16), 256>>>();
    ctx_kernel<<<dim3(NC, BH), 128, CTX_SMEM_BYTES>>>();
    gemm_tf32<1><<<dim3(4, 32), 256, GEMM_SMEM_BYTES>>>(bo, nullptr, out);
}

// round 8
// speedup vs baseline: 5.8830x; 1.5198x over previous
#include <cuda_runtime.h>
#include <cuda_fp16.h>
#include <math.h>
#include <stdint.h>

// Problem constants
#define BB 2
#define SS 2048
#define DM 512
#define HH 8
#define DH 64
#define CH 64               // chunk length
#define NC (SS/CH)          // 32 chunks
#define BH (BB*HH)          // 16 (b,h) pairs

// Scratch (device globals)
__device__ __half g_qh  [BH*SS*DH];     // elu+1, fp16
__device__ __half g_kh  [BH*SS*DH];
__device__ __half g_vh  [BH*SS*DH];
__device__ __half g_ckvh[BH*NC*DH*DH];  // per-chunk (V^T K): [d][e]
__device__ float  g_cks [BH*NC*DH];
__device__ __half g_pkvh[BH*NC*DH*DH];  // exclusive prefix (still [d][e])
__device__ float  g_pks [BH*NC*DH];
__device__ __half g_ctxh[BB*SS*DM];     // context fp16
__device__ __half g_xh  [BB*SS*DM];     // x fp16
__device__ __half g_wh  [3*DM*DM];      // [Wqk ; Wv] fp16
__device__ __half g_woh [DM*DM];        // Wo fp16

// ===========================================================================
// helpers
// ===========================================================================
__device__ __forceinline__ uint32_t smem_u32(const void* p) {
    uint32_t a;
    asm("{ .reg .u64 t; cvta.to.shared.u64 t, %1; cvt.u32.u64 %0, t; }"
        : "=r"(a) : "l"(p));
    return a;
}
__device__ __forceinline__ void ldsm_x4(uint32_t& r0, uint32_t& r1,
                                        uint32_t& r2, uint32_t& r3, uint32_t a) {
    asm volatile("ldmatrix.sync.aligned.m8n8.x4.shared.b16 {%0,%1,%2,%3}, [%4];"
                 : "=r"(r0), "=r"(r1), "=r"(r2), "=r"(r3) : "r"(a));
}
__device__ __forceinline__ void ldsm_x2(uint32_t& r0, uint32_t& r1, uint32_t a) {
    asm volatile("ldmatrix.sync.aligned.m8n8.x2.shared.b16 {%0,%1}, [%2];"
                 : "=r"(r0), "=r"(r1) : "r"(a));
}
__device__ __forceinline__ void mma_f16(float& c0, float& c1, float& c2, float& c3,
                                        uint32_t a0, uint32_t a1, uint32_t a2, uint32_t a3,
                                        uint32_t b0, uint32_t b1) {
    asm volatile("mma.sync.aligned.m16n8k16.row.col.f32.f16.f16.f32 "
                 "{%0,%1,%2,%3}, {%4,%5,%6,%7}, {%8,%9}, {%0,%1,%2,%3};"
                 : "+f"(c0), "+f"(c1), "+f"(c2), "+f"(c3)
                 : "r"(a0), "r"(a1), "r"(a2), "r"(a3), "r"(b0), "r"(b1));
}
#define CP16(dst, src) \
    asm volatile("cp.async.cg.shared.global [%0], [%1], 16;" \
                 :: "r"(dst), "l"(src) : "memory")
#define CP_COMMIT() asm volatile("cp.async.commit_group;" ::: "memory")
#define CP_WAIT2()  asm volatile("cp.async.wait_group 2;" ::: "memory")

// ===========================================================================
// Kernel 0: convert inputs to fp16.
// ===========================================================================
__global__ __launch_bounds__(256) void round_kernel(
    const float* __restrict__ x, const float* __restrict__ Wqk,
    const float* __restrict__ Wv, const float* __restrict__ Wo)
{
    const int tid = blockIdx.x * 256 + threadIdx.x;
    const int stride = gridDim.x * 256;
    const float2* x2 = (const float2*)x;
    __half2* xo = (__half2*)g_xh;
    for (int i = tid; i < BB*SS*DM/2; i += stride) xo[i] = __float22half2_rn(x2[i]);
    const float2* a2 = (const float2*)Wqk;
    __half2* ao = (__half2*)g_wh;
    for (int i = tid; i < 2*DM*DM/2; i += stride) ao[i] = __float22half2_rn(a2[i]);
    const float2* b2 = (const float2*)Wv;
    __half2* bo = (__half2*)(g_wh + 2*DM*DM);
    for (int i = tid; i < DM*DM/2; i += stride) bo[i] = __float22half2_rn(b2[i]);
    const float2* c2 = (const float2*)Wo;
    __half2* co = (__half2*)g_woh;
    for (int i = tid; i < DM*DM/2; i += stride) co[i] = __float22half2_rn(c2[i]);
}

// ===========================================================================
// fp16 mma.sync GEMM, cp.async 4-stage pipeline.
// C[128x128] = A[128xK] * B[128xK]^T (NT), K=512, BK=32 halves.
// 256 threads = 8 warps (2M x 4N), warp tile 64x32, frags m16n8k16.
// smem rows: 32 halves + 8 pad = 80 B (conflict-free ldmatrix).
// MODE 0: proj (A=g_xh, B=g_wh, bias+elu, scatter q/k/v fp16)
// MODE 1: out  (A=g_ctxh, B=g_woh, bias, store fp32 out)
// ===========================================================================
#define BKH 32
#define ROWB 80
#define TILEBH (128*ROWB)                  // 10240
#define STAGEBH (2*TILEBH)                 // 20480
#define NST 4
#define GEMM_SMEM_BYTES (NST*STAGEBH)      // 81920

template<int MODE>
__global__ __launch_bounds__(256, 2) void gemm_f16(
    const float* __restrict__ bias0, const float* __restrict__ bias1,
    float* __restrict__ outp)
{
    extern __shared__ __align__(16) char smem[];
    const int tid = threadIdx.x;
    const int wid = tid >> 5, lane = tid & 31;
    const int wm = wid & 1, wn = wid >> 1;
    const int jt = blockIdx.x * 128;
    const int nt = blockIdx.y * 128;

    const __half* Ap = (MODE == 1) ? (const __half*)g_ctxh : (const __half*)g_xh;
    const __half* Bp = (MODE == 1) ? (const __half*)g_woh  : (const __half*)g_wh;

    const uint32_t sb = smem_u32(smem);

    // per-thread gmem rows + smem dst (2 x 16B for A, 2 for B per K-tile)
    const __half* rowA[2]; const __half* rowB[2]; uint32_t dA[2], dB[2];
#pragma unroll
    for (int u = 0; u < 2; u++) {
        int idx = tid + u * 256;            // 0..511
        int r = idx >> 2, c = idx & 3;      // row 0..127, 16B chunk 0..3
        dA[u] = (uint32_t)(r * ROWB + c * 16);
        dB[u] = dA[u] + TILEBH;
        rowA[u] = Ap + (size_t)(nt + r) * DM + c * 8;
        rowB[u] = Bp + (size_t)(jt + r) * DM + c * 8;
    }

    // ldmatrix lane offsets
    const uint32_t aoff = (uint32_t)((lane & 15) * ROWB + (lane >> 4) * 16
                                     + wm * 64 * ROWB);
    const uint32_t boff = (uint32_t)((lane & 7) * ROWB + ((lane >> 3) & 1) * 16
                                     + wn * 32 * ROWB) + TILEBH;

    float acc[4][4][4] = {};

    // prologue: stages 0..2
#pragma unroll
    for (int s = 0; s < 3; s++) {
        const uint32_t st = sb + s * STAGEBH;
        const int k0 = s * BKH;
#pragma unroll
        for (int u = 0; u < 2; u++) {
            CP16(st + dA[u], rowA[u] + k0);
            CP16(st + dB[u], rowB[u] + k0);
        }
        CP_COMMIT();
    }

    for (int it = 0; it < 16; it++) {
        const int buf = it & 3;
        CP_WAIT2();
        __syncthreads();
        const uint32_t abase = sb + buf * STAGEBH + aoff;
        const uint32_t bbase = sb + buf * STAGEBH + boff;
#pragma unroll
        for (int kk = 0; kk < 2; kk++) {
            uint32_t afr[4][4], bfr[4][2];
#pragma unroll
            for (int mf = 0; mf < 4; mf++)
                ldsm_x4(afr[mf][0], afr[mf][1], afr[mf][2], afr[mf][3],
                        abase + (uint32_t)(mf * 16 * ROWB) + kk * 32);
#pragma unroll
            for (int nf = 0; nf < 4; nf++)
                ldsm_x2(bfr[nf][0], bfr[nf][1],
                        bbase + (uint32_t)(nf * 8 * ROWB) + kk * 32);
#pragma unroll
            for (int mf = 0; mf < 4; mf++)
#pragma unroll
                for (int nf = 0; nf < 4; nf++)
                    mma_f16(acc[mf][nf][0], acc[mf][nf][1],
                            acc[mf][nf][2], acc[mf][nf][3],
                            afr[mf][0], afr[mf][1], afr[mf][2], afr[mf][3],
                            bfr[nf][0], bfr[nf][1]);
        }
        __syncthreads();
        const int nxt = it + 3;
        if (nxt < 16) {
            const uint32_t st = sb + (nxt & 3) * STAGEBH;
            const int k0 = nxt * BKH;
#pragma unroll
            for (int u = 0; u < 2; u++) {
                CP16(st + dA[u], rowA[u] + k0);
                CP16(st + dB[u], rowB[u] + k0);
            }
        }
        CP_COMMIT();
    }

    const int rl = lane >> 2, cl = (lane & 3) * 2;
#pragma unroll
    for (int mf = 0; mf < 4; mf++) {
#pragma unroll
        for (int nf = 0; nf < 4; nf++) {
            const int j0 = jt + wn * 32 + nf * 8 + cl;
#pragma unroll
            for (int half = 0; half < 2; half++) {
                const int row = nt + wm * 64 + mf * 16 + rl + half * 8;
                float v0 = acc[mf][nf][half * 2 + 0];
                float v1 = acc[mf][nf][half * 2 + 1];
                if (MODE == 0) {
                    const int b_ = row >> 11, s_ = row & (SS - 1);
                    if (j0 < 2 * DM) {
                        v0 += bias0[j0]; v1 += bias0[j0 + 1];
                        v0 = (v0 > 0.f) ? v0 + 1.f : expf(v0);
                        v1 = (v1 > 0.f) ? v1 + 1.f : expf(v1);
                        int jm = j0 & (DM - 1);
                        int h = jm >> 6, d = jm & 63;
                        __half* dst = (j0 < DM ? g_qh : g_kh)
                                    + (((size_t)(b_ * HH + h) * SS + s_) * DH + d);
                        *(__half2*)dst = __floats2half2_rn(v0, v1);
                    } else {
                        int jm = j0 - 2 * DM;
                        v0 += bias1[jm]; v1 += bias1[jm + 1];
                        int h = jm >> 6, d = jm & 63;
                        __half* dst = g_vh + (((size_t)(b_ * HH + h) * SS + s_) * DH + d);
                        *(__half2*)dst = __floats2half2_rn(v0, v1);
                    }
                } else {
                    float2 bi = *(const float2*)(bias0 + j0);
                    *(float2*)(outp + (size_t)row * DM + j0) =
                        make_float2(v0 + bi.x, v1 + bi.y);
                }
            }
        }
    }
}

// ===========================================================================
// Kernel 2: per-chunk M[d][e] = sum_s v[s][d] k[s][e]  (A=v^T, B=k^T), fp16.
// 128 threads = 4 warps (2x2), warp tile 32x32, K=s=64 -> 4 k16 steps.
// Tile rows: 64 halves + 8 pad = 144 B.
// ===========================================================================
#define TPH 72
#define TPHB 144

__global__ __launch_bounds__(128) void chunkkv_kernel()
{
    __shared__ __half sKT[64*TPH];
    __shared__ __half sVT[64*TPH];
    const int c  = blockIdx.x, bh = blockIdx.y;
    const int tid = threadIdx.x;
    const int wid = tid >> 5, lane = tid & 31;
    const int wm = wid & 1, wn = wid >> 1;
    const __half* kp = g_kh + ((size_t)bh*SS + (size_t)c*CH)*DH;
    const __half* vp = g_vh + ((size_t)bh*SS + (size_t)c*CH)*DH;

    for (int idx = tid; idx < 2048; idx += 128) {
        int r = idx >> 5, c2 = idx & 31;
        __half2 k2 = *(const __half2*)(kp + r*DH + 2*c2);
        sKT[(2*c2+0)*TPH + r] = __low2half(k2);
        sKT[(2*c2+1)*TPH + r] = __high2half(k2);
        __half2 v2 = *(const __half2*)(vp + r*DH + 2*c2);
        sVT[(2*c2+0)*TPH + r] = __low2half(v2);
        sVT[(2*c2+1)*TPH + r] = __high2half(v2);
    }
    __syncthreads();

    const uint32_t aoff = (uint32_t)((lane & 15) * TPHB + (lane >> 4) * 16);
    const uint32_t boff = (uint32_t)((lane & 7) * TPHB + ((lane >> 3) & 1) * 16);
    const uint32_t abase = smem_u32(sVT) + (uint32_t)(wm * 32 * TPHB) + aoff;
    const uint32_t bbase = smem_u32(sKT) + (uint32_t)(wn * 32 * TPHB) + boff;

    float acc[2][4][4] = {};
#pragma unroll
    for (int kk = 0; kk < 4; kk++) {
        uint32_t afr[2][4], bfr[4][2];
#pragma unroll
        for (int mf = 0; mf < 2; mf++)
            ldsm_x4(afr[mf][0], afr[mf][1], afr[mf][2], afr[mf][3],
                    abase + (uint32_t)(mf * 16 * TPHB) + kk * 32);
#pragma unroll
        for (int nf = 0; nf < 4; nf++)
            ldsm_x2(bfr[nf][0], bfr[nf][1],
                    bbase + (uint32_t)(nf * 8 * TPHB) + kk * 32);
#pragma unroll
        for (int mf = 0; mf < 2; mf++)
#pragma unroll
            for (int nf = 0; nf < 4; nf++)
                mma_f16(acc[mf][nf][0], acc[mf][nf][1],
                        acc[mf][nf][2], acc[mf][nf][3],
                        afr[mf][0], afr[mf][1], afr[mf][2], afr[mf][3],
                        bfr[nf][0], bfr[nf][1]);
    }

    __half* dst = g_ckvh + ((size_t)bh*NC + c)*DH*DH;
    const int rl = lane >> 2, cl = (lane & 3) * 2;
#pragma unroll
    for (int mf = 0; mf < 2; mf++)
#pragma unroll
        for (int nf = 0; nf < 4; nf++)
#pragma unroll
            for (int half = 0; half < 2; half++) {
                int row = wm*32 + mf*16 + rl + half*8;   // d
                int col = wn*32 + nf*8 + cl;             // e
                *(__half2*)(dst + row*DH + col) =
                    __floats2half2_rn(acc[mf][nf][half*2], acc[mf][nf][half*2+1]);
            }

    if (tid < DH) {
        float s = 0.f;
#pragma unroll 8
        for (int r = 0; r < CH; r++) s += __half2float(sKT[tid*TPH + r]);
        g_cks[((size_t)bh*NC + c)*DH + tid] = s;
    }
}

// ===========================================================================
// Kernel 3: exclusive prefix scan (fp32 accumulate, fp16 storage).
// ===========================================================================
__global__ __launch_bounds__(256) void scan_kernel()
{
    const int bh = blockIdx.x;
    const int tid = threadIdx.x;
    const int e = blockIdx.y * 256 + tid;       // 0..4095
    const size_t base = (size_t)bh * NC;
    __half v[NC];
#pragma unroll
    for (int c = 0; c < NC; c++)
        v[c] = g_ckvh[(base + c) * (DH*DH) + e];
    float run = 0.f;
#pragma unroll
    for (int c = 0; c < NC; c++) {
        g_pkvh[(base + c) * (DH*DH) + e] = __float2half_rn(run);
        run += __half2float(v[c]);
    }
    if (blockIdx.y == 0 && tid < DH) {
        float w[NC];
#pragma unroll
        for (int c = 0; c < NC; c++) w[c] = g_cks[(base + c)*DH + tid];
        float r = 0.f;
#pragma unroll
        for (int c = 0; c < NC; c++) {
            g_pks[(base + c)*DH + tid] = r;
            r += w[c];
        }
    }
}

// ===========================================================================
// Kernel 4: per-chunk context, fp16 mma.
//  S = q k^T (mask) ; den = rowsum(S_h) + q.ks_pre
//  ctx = (S_h @ v + q @ KV_pre) / den
// ===========================================================================
__global__ __launch_bounds__(128) void ctx_kernel()
{
    __shared__ __half sQ  [64*TPH];   // [t][e]
    __shared__ __half sK  [64*TPH];   // [s][e]
    __shared__ __half sS  [64*TPH];   // [t][s] masked fp16
    __shared__ __half sVT [64*TPH];   // [d][s]
    __shared__ __half sKVT[64*TPH];   // [d][e]
    __shared__ float  sKs [64];
    __shared__ float  sDen[64];

    const int c  = blockIdx.x, bh = blockIdx.y;
    const int tid = threadIdx.x;
    const int wid = tid >> 5, lane = tid & 31;
    const int wm = wid & 1, wn = wid >> 1;

    const __half* qp  = g_qh   + ((size_t)bh*SS + (size_t)c*CH)*DH;
    const __half* kp  = g_kh   + ((size_t)bh*SS + (size_t)c*CH)*DH;
    const __half* vp  = g_vh   + ((size_t)bh*SS + (size_t)c*CH)*DH;
    const __half* kvp = g_pkvh + ((size_t)bh*NC + c)*DH*DH;
    const float*  ksp = g_pks  + ((size_t)bh*NC + c)*DH;

    for (int idx = tid; idx < 2048; idx += 128) {
        int r = idx >> 5, c2 = idx & 31;
        *(__half2*)&sQ[r*TPH + 2*c2]   = *(const __half2*)(qp  + r*DH + 2*c2);
        *(__half2*)&sK[r*TPH + 2*c2]   = *(const __half2*)(kp  + r*DH + 2*c2);
        *(__half2*)&sKVT[r*TPH + 2*c2] = *(const __half2*)(kvp + r*DH + 2*c2);
        __half2 v2 = *(const __half2*)(vp + r*DH + 2*c2);
        sVT[(2*c2+0)*TPH + r] = __low2half(v2);
        sVT[(2*c2+1)*TPH + r] = __high2half(v2);
    }
    if (tid < DH) sKs[tid] = ksp[tid];
    __syncthreads();

    const uint32_t aoff = (uint32_t)((lane & 15) * TPHB + (lane >> 4) * 16);
    const uint32_t boff = (uint32_t)((lane & 7) * TPHB + ((lane >> 3) & 1) * 16);
    const uint32_t awm = (uint32_t)(wm * 32 * TPHB);
    const uint32_t bwn = (uint32_t)(wn * 32 * TPHB);
    const int rl = lane >> 2, cl = (lane & 3) * 2;

    // ---- mma1: S = q . k^T ----
    {
        const uint32_t abase = smem_u32(sQ) + awm + aoff;
        const uint32_t bbase = smem_u32(sK) + bwn + boff;
        float acc[2][4][4] = {};
#pragma unroll
        for (int kk = 0; kk < 4; kk++) {
            uint32_t afr[2][4], bfr[4][2];
#pragma unroll
            for (int mf = 0; mf < 2; mf++)
                ldsm_x4(afr[mf][0], afr[mf][1], afr[mf][2], afr[mf][3],
                        abase + (uint32_t)(mf * 16 * TPHB) + kk * 32);
#pragma unroll
            for (int nf = 0; nf < 4; nf++)
                ldsm_x2(bfr[nf][0], bfr[nf][1],
                        bbase + (uint32_t)(nf * 8 * TPHB) + kk * 32);
#pragma unroll
            for (int mf = 0; mf < 2; mf++)
#pragma unroll
                for (int nf = 0; nf < 4; nf++)
                    mma_f16(acc[mf][nf][0], acc[mf][nf][1],
                            acc[mf][nf][2], acc[mf][nf][3],
                            afr[mf][0], afr[mf][1], afr[mf][2], afr[mf][3],
                            bfr[nf][0], bfr[nf][1]);
        }
#pragma unroll
        for (int mf = 0; mf < 2; mf++)
#pragma unroll
            for (int nf = 0; nf < 4; nf++)
#pragma unroll
                for (int half = 0; half < 2; half++) {
                    int t = wm*32 + mf*16 + rl + half*8;
                    int s = wn*32 + nf*8 + cl;
                    float v0 = (s   <= t) ? acc[mf][nf][half*2]   : 0.f;
                    float v1 = (s+1 <= t) ? acc[mf][nf][half*2+1] : 0.f;
                    *(__half2*)&sS[t*TPH + s] = __floats2half2_rn(v0, v1);
                }
    }
    __syncthreads();

    // den (fp32, from fp16-rounded S for num/den consistency)
    if (tid < DH) {
        float d = 0.f;
#pragma unroll 8
        for (int s = 0; s < CH; s++) d += __half2float(sS[tid*TPH + s]);
#pragma unroll 8
        for (int e = 0; e < DH; e++)
            d += __half2float(sQ[tid*TPH + e]) * sKs[e];
        sDen[tid] = d;
    }

    // ---- mma2+3: ctx = S @ v + q @ KV_pre ----
    float acc[2][4][4] = {};
    {
        const uint32_t a1 = smem_u32(sS) + awm + aoff;
        const uint32_t b1 = smem_u32(sVT) + bwn + boff;
#pragma unroll
        for (int kk = 0; kk < 4; kk++) {
            uint32_t afr[2][4], bfr[4][2];
#pragma unroll
            for (int mf = 0; mf < 2; mf++)
                ldsm_x4(afr[mf][0], afr[mf][1], afr[mf][2], afr[mf][3],
                        a1 + (uint32_t)(mf * 16 * TPHB) + kk * 32);
#pragma unroll
            for (int nf = 0; nf < 4; nf++)
                ldsm_x2(bfr[nf][0], bfr[nf][1],
                        b1 + (uint32_t)(nf * 8 * TPHB) + kk * 32);
#pragma unroll
            for (int mf = 0; mf < 2; mf++)
#pragma unroll
                for (int nf = 0; nf < 4; nf++)
                    mma_f16(acc[mf][nf][0], acc[mf][nf][1],
                            acc[mf][nf][2], acc[mf][nf][3],
                            afr[mf][0], afr[mf][1], afr[mf][2], afr[mf][3],
                            bfr[nf][0], bfr[nf][1]);
        }
        const uint32_t a2 = smem_u32(sQ) + awm + aoff;
        const uint32_t b2 = smem_u32(sKVT) + bwn + boff;
#pragma unroll
        for (int kk = 0; kk < 4; kk++) {
            uint32_t afr[2][4], bfr[4][2];
#pragma unroll
            for (int mf = 0; mf < 2; mf++)
                ldsm_x4(afr[mf][0], afr[mf][1], afr[mf][2], afr[mf][3],
                        a2 + (uint32_t)(mf * 16 * TPHB) + kk * 32);
#pragma unroll
            for (int nf = 0; nf < 4; nf++)
                ldsm_x2(bfr[nf][0], bfr[nf][1],
                        b2 + (uint32_t)(nf * 8 * TPHB) + kk * 32);
#pragma unroll
            for (int mf = 0; mf < 2; mf++)
#pragma unroll
                for (int nf = 0; nf < 4; nf++)
                    mma_f16(acc[mf][nf][0], acc[mf][nf][1],
                            acc[mf][nf][2], acc[mf][nf][3],
                            afr[mf][0], afr[mf][1], afr[mf][2], afr[mf][3],
                            bfr[nf][0], bfr[nf][1]);
        }
    }
    __syncthreads();   // sDen visibility

    const int b_ = bh >> 3, h = bh & 7;
#pragma unroll
    for (int mf = 0; mf < 2; mf++)
#pragma unroll
        for (int nf = 0; nf < 4; nf++)
#pragma unroll
            for (int half = 0; half < 2; half++) {
                int t = wm*32 + mf*16 + rl + half*8;
                int d = wn*32 + nf*8 + cl;
                float inv = 1.f / sDen[t];
                int sg = c*CH + t;
                *(__half2*)(g_ctxh + ((size_t)(b_*SS + sg))*DM + h*DH + d) =
                    __floats2half2_rn(acc[mf][nf][half*2]   * inv,
                                      acc[mf][nf][half*2+1] * inv);
            }
}

// ---------------------------------------------------------------------------
extern "C" void kernel_launch(void* const* d_in, const int* in_sizes, int n_in,
                              void* d_out, int out_size)
{
    const float* x   = (const float*)d_in[0];
    const float* Wqk = (const float*)d_in[1];
    const float* bqk = (const float*)d_in[2];
    const float* Wv  = (const float*)d_in[3];
    const float* bv  = (const float*)d_in[4];
    const float* Wo  = (const float*)d_in[5];
    const float* bo  = (const float*)d_in[6];
    float* out = (float*)d_out;

    cudaFuncSetAttribute(gemm_f16<0>,
        cudaFuncAttributeMaxDynamicSharedMemorySize, GEMM_SMEM_BYTES);
    cudaFuncSetAttribute(gemm_f16<1>,
        cudaFuncAttributeMaxDynamicSharedMemorySize, GEMM_SMEM_BYTES);

    round_kernel<<<592, 256>>>(x, Wqk, Wv, Wo);
    gemm_f16<0><<<dim3(12, 32), 256, GEMM_SMEM_BYTES>>>(bqk, bv, nullptr);
    chunkkv_kernel<<<dim3(NC, BH), 128>>>();
    scan_kernel<<<dim3(BH, 16), 256>>>();
    ctx_kernel<<<dim3(NC, BH), 128>>>();
    gemm_f16<1><<<dim3(4, 32), 256, GEMM_SMEM_BYTES>>>(bo, nullptr, out);
}